// round 1
// baseline (speedup 1.0000x reference)
#include <cuda_runtime.h>
#include <math.h>

#define B 2
#define S 2048
#define D 1024
#define H 16
#define HD 64

// ---------------- scratch (allocation-free) ----------------
__device__ float g_q[B * S * D];      // 16 MB  q projection (roped in place)
__device__ float g_k[B * S * HD];     // 1 MB
__device__ float g_v[B * S * HD];     // 1 MB
__device__ float g_att[B * S * D];    // 16 MB  attention output

// ---------------- tiled SGEMM ----------------
// C[m,n] = sum_k A[m,k] * (BT ? Bm[n,k] : Bm[k,n])
// 64x64 tile per block, BK=16, 256 threads, 4x4 micro-tile.
template <bool BT>
__global__ void gemm64(const float* __restrict__ A, const float* __restrict__ Bm,
                       float* __restrict__ C, int M, int N, int K) {
    __shared__ float As[16][65];
    __shared__ float Bs[16][65];

    const int bm = blockIdx.y * 64;
    const int bn = blockIdx.x * 64;
    const int tx = threadIdx.x, ty = threadIdx.y;
    const int tid = ty * 16 + tx;

    float acc[4][4] = {};

    for (int k0 = 0; k0 < K; k0 += 16) {
#pragma unroll
        for (int i = tid; i < 64 * 16; i += 256) {
            int r = i >> 4;      // 0..63
            int c = i & 15;      // 0..15
            As[c][r] = A[(bm + r) * K + k0 + c];
            Bs[c][r] = BT ? Bm[(bn + r) * K + k0 + c]
                          : Bm[(k0 + c) * N + bn + r];
        }
        __syncthreads();
#pragma unroll
        for (int kk = 0; kk < 16; kk++) {
            float a[4], bb[4];
#pragma unroll
            for (int i = 0; i < 4; i++) a[i] = As[kk][ty * 4 + i];
#pragma unroll
            for (int j = 0; j < 4; j++) bb[j] = Bs[kk][tx * 4 + j];
#pragma unroll
            for (int i = 0; i < 4; i++)
#pragma unroll
                for (int j = 0; j < 4; j++) acc[i][j] += a[i] * bb[j];
        }
        __syncthreads();
    }
#pragma unroll
    for (int i = 0; i < 4; i++)
#pragma unroll
        for (int j = 0; j < 4; j++)
            C[(bm + ty * 4 + i) * N + bn + tx * 4 + j] = acc[i][j];
}

// ---------------- RoPE (in-place, one warp-half... one 32-lane group per 64-chunk) ----------------
// out[i]    = t[2i]*cos_i - t[2i+1]*sin_i        (i in 0..31)
// out[32+i] = t[2i+1]*cos_i + t[2i]*sin_i
// q chunks: (b*S+s)*H + h ; k chunks appended after.
__global__ void rope_kernel(float* __restrict__ q, float* __restrict__ k) {
    const long total = (long)B * S * (H + 1) * 32;
    long gtid = (long)blockIdx.x * blockDim.x + threadIdx.x;
    if (gtid >= total) return;
    int lane = (int)(gtid & 31);
    long chunk = gtid >> 5;
    const long nq = (long)B * S * H;

    float* base;
    int s;
    if (chunk < nq) {
        s = (int)((chunk / H) % S);
        base = q + chunk * 64;
    } else {
        long c2 = chunk - nq;
        s = (int)(c2 % S);
        base = k + c2 * 64;
    }
    float freq = powf(1000.0f, -(float)lane / 32.0f);
    float ang = (float)s * freq;
    float sn, cs;
    sincosf(ang, &sn, &cs);
    float t0 = base[2 * lane];
    float t1 = base[2 * lane + 1];
    __syncwarp();
    base[lane]      = t0 * cs - t1 * sn;
    base[lane + 32] = t1 * cs + t0 * sn;
}

// ---------------- flash attention (fp32, causal, MQA) ----------------
// grid: (S/64, H, B). 256 threads (16x16), 4x4 micro-tiles.
// smem: Q[64][65], K[64][65], V[64][65], P[64][65] = 66560 B dynamic.
__global__ void attn_kernel(const float* __restrict__ q, const float* __restrict__ k,
                            const float* __restrict__ v, float* __restrict__ o) {
    extern __shared__ float sm[];
    float* Qs = sm;                // [64][65]
    float* Ks = sm + 64 * 65;      // [64][65]
    float* Vs = sm + 2 * 64 * 65;  // [64][65]  Vs[ki][d]
    float* Ps = sm + 3 * 64 * 65;  // [64][65]

    const int b = blockIdx.z, h = blockIdx.y, qt = blockIdx.x;
    const int tx = threadIdx.x, ty = threadIdx.y;
    const int tid = ty * 16 + tx;
    const float scale = 0.125f;  // 1/sqrt(64)

    const float* qb = q + ((long)b * S + qt * 64) * D + h * 64;
#pragma unroll
    for (int i = tid; i < 64 * 64; i += 256) {
        int r = i >> 6, c = i & 63;
        Qs[r * 65 + c] = qb[r * D + c] * scale;
    }

    float m[4], l[4], acc[4][4];
#pragma unroll
    for (int i = 0; i < 4; i++) {
        m[i] = -1e30f;
        l[i] = 0.0f;
#pragma unroll
        for (int j = 0; j < 4; j++) acc[i][j] = 0.0f;
    }

    for (int kt = 0; kt <= qt; kt++) {
        const float* kb = k + ((long)b * S + kt * 64) * HD;
        const float* vb = v + ((long)b * S + kt * 64) * HD;
#pragma unroll
        for (int i = tid; i < 64 * 64; i += 256) {
            int r = i >> 6, c = i & 63;
            Ks[r * 65 + c] = kb[r * HD + c];
            Vs[r * 65 + c] = vb[r * HD + c];
        }
        __syncthreads();

        // S tile = Qs * Ks^T
        float sv[4][4] = {};
#pragma unroll
        for (int kk = 0; kk < 64; kk++) {
            float a[4], bb[4];
#pragma unroll
            for (int i = 0; i < 4; i++) a[i] = Qs[(ty * 4 + i) * 65 + kk];
#pragma unroll
            for (int j = 0; j < 4; j++) bb[j] = Ks[(tx * 4 + j) * 65 + kk];
#pragma unroll
            for (int i = 0; i < 4; i++)
#pragma unroll
                for (int j = 0; j < 4; j++) sv[i][j] += a[i] * bb[j];
        }
        // causal mask (only diagonal tile)
        if (kt == qt) {
#pragma unroll
            for (int i = 0; i < 4; i++)
#pragma unroll
                for (int j = 0; j < 4; j++)
                    if (tx * 4 + j > ty * 4 + i) sv[i][j] = -1e30f;
        }

        // online softmax: rows distributed over the 16-lane tx group
#pragma unroll
        for (int i = 0; i < 4; i++) {
            float rm = sv[i][0];
#pragma unroll
            for (int j = 1; j < 4; j++) rm = fmaxf(rm, sv[i][j]);
#pragma unroll
            for (int off = 8; off > 0; off >>= 1)
                rm = fmaxf(rm, __shfl_xor_sync(0xffffffffu, rm, off));
            float m_new = fmaxf(m[i], rm);
            float rs = 0.0f;
            float p[4];
#pragma unroll
            for (int j = 0; j < 4; j++) {
                p[j] = expf(sv[i][j] - m_new);
                rs += p[j];
            }
#pragma unroll
            for (int off = 8; off > 0; off >>= 1)
                rs += __shfl_xor_sync(0xffffffffu, rs, off);
            float alpha = expf(m[i] - m_new);
            l[i] = l[i] * alpha + rs;
#pragma unroll
            for (int j = 0; j < 4; j++) {
                acc[i][j] *= alpha;
                Ps[(ty * 4 + i) * 65 + tx * 4 + j] = p[j];
            }
            m[i] = m_new;
        }
        __syncthreads();

        // O += P * V
#pragma unroll
        for (int kk = 0; kk < 64; kk++) {
            float a[4], bv[4];
#pragma unroll
            for (int i = 0; i < 4; i++) a[i] = Ps[(ty * 4 + i) * 65 + kk];
#pragma unroll
            for (int j = 0; j < 4; j++) bv[j] = Vs[kk * 65 + tx * 4 + j];
#pragma unroll
            for (int i = 0; i < 4; i++)
#pragma unroll
                for (int j = 0; j < 4; j++) acc[i][j] += a[i] * bv[j];
        }
        __syncthreads();
    }

    float* ob = o + ((long)b * S + qt * 64) * D + h * 64;
#pragma unroll
    for (int i = 0; i < 4; i++) {
        float inv = 1.0f / l[i];
#pragma unroll
        for (int j = 0; j < 4; j++)
            ob[(ty * 4 + i) * D + tx * 4 + j] = acc[i][j] * inv;
    }
}

// ---------------- launch ----------------
extern "C" void kernel_launch(void* const* d_in, const int* in_sizes, int n_in,
                              void* d_out, int out_size) {
    const float* x  = (const float*)d_in[0];
    const float* wq = (const float*)d_in[1];
    const float* wk = (const float*)d_in[2];
    const float* wv = (const float*)d_in[3];
    const float* wo = (const float*)d_in[4];
    float* out = (float*)d_out;

    float *qp, *kp, *vp, *ap;
    cudaGetSymbolAddress((void**)&qp, g_q);
    cudaGetSymbolAddress((void**)&kp, g_k);
    cudaGetSymbolAddress((void**)&vp, g_v);
    cudaGetSymbolAddress((void**)&ap, g_att);

    dim3 thr(16, 16);
    const int M = B * S;  // 4096

    // Q = x @ wq^T   (wq is [D,D] row-major: C[m,n] = sum_k x[m,k]*wq[n,k])
    gemm64<true><<<dim3(D / 64, M / 64), thr>>>(x, wq, qp, M, D, D);
    // K = x @ wk, V = x @ wv  ([D,HD])
    gemm64<false><<<dim3(HD / 64, M / 64), thr>>>(x, wk, kp, M, HD, D);
    gemm64<false><<<dim3(HD / 64, M / 64), thr>>>(x, wv, vp, M, HD, D);

    // RoPE in place on q (per head) and k
    {
        long total = (long)B * S * (H + 1) * 32;
        int threads = 256;
        long blocks = (total + threads - 1) / threads;
        rope_kernel<<<(unsigned)blocks, threads>>>(qp, kp);
    }

    // flash attention
    {
        const int smem = 4 * 64 * 65 * (int)sizeof(float);  // 66560
        cudaFuncSetAttribute(attn_kernel, cudaFuncAttributeMaxDynamicSharedMemorySize, smem);
        attn_kernel<<<dim3(S / 64, H, B), thr, smem>>>(qp, kp, vp, ap);
    }

    // out = att @ wo^T
    gemm64<true><<<dim3(D / 64, M / 64), thr>>>(ap, wo, out, M, D, D);
}

// round 3
// speedup vs baseline: 2.8375x; 2.8375x over previous
#include <cuda_runtime.h>
#include <math.h>
#include <stdint.h>

#define B 2
#define S 2048
#define D 1024
#define H 16
#define HD 64

// ---------------- scratch (allocation-free) ----------------
__device__ float g_q[B * S * D];      // 16 MB
__device__ float g_k[B * S * HD];     // 1 MB
__device__ float g_v[B * S * HD];     // 1 MB
__device__ float g_att[B * S * D];    // 16 MB
__device__ float g_wqt[D * D];        // 4 MB  wq^T
__device__ float g_wot[D * D];        // 4 MB  wo^T

// ---------------- helpers ----------------
__device__ __forceinline__ unsigned f2tf(float x) {
    unsigned r;
    asm("cvt.rna.tf32.f32 %0, %1;" : "=r"(r) : "f"(x));
    return r;
}

__device__ __forceinline__ void mma8(float* c, const unsigned* a, const unsigned* b) {
    asm volatile(
        "mma.sync.aligned.m16n8k8.row.col.f32.tf32.tf32.f32 "
        "{%0,%1,%2,%3}, {%4,%5,%6,%7}, {%8,%9}, {%0,%1,%2,%3};"
        : "+f"(c[0]), "+f"(c[1]), "+f"(c[2]), "+f"(c[3])
        : "r"(a[0]), "r"(a[1]), "r"(a[2]), "r"(a[3]), "r"(b[0]), "r"(b[1]));
}

#define CPA16(dst, src) \
    asm volatile("cp.async.cg.shared.global [%0], [%1], 16;" ::"r"(dst), "l"(src))

// ---------------- 1024x1024 transpose (wq, wo) ----------------
__global__ void tr1024(const float* __restrict__ a, const float* __restrict__ b,
                       float* __restrict__ ta, float* __restrict__ tb) {
    const float* in = blockIdx.z ? b : a;
    float* out = blockIdx.z ? tb : ta;
    __shared__ float t[32][33];
    int x = blockIdx.x * 32 + threadIdx.x;
    int y0 = blockIdx.y * 32;
    for (int i = threadIdx.y; i < 32; i += 8)
        t[i][threadIdx.x] = in[(y0 + i) * 1024 + x];
    __syncthreads();
    int x2 = y0 + threadIdx.x;
    int y2 = blockIdx.x * 32;
    for (int i = threadIdx.y; i < 32; i += 8)
        out[(y2 + i) * 1024 + x2] = t[threadIdx.x][i];
}

// ---------------- tf32 tensor-core GEMM ----------------
// C[M,N] = A[M,K] * Bg[K,N]   (Bg row-major [K][N])
// BM=128, BK=32, BN template. 256 threads = 8 warps (4 m x 2 n).
// KV mode: blockIdx.x selects (B0,C0)/(B1,C1), bn=0 (N=64 dual projection).
template <int BN, bool KV>
__global__ void gemm_tc(const float* __restrict__ A, const float* __restrict__ B0,
                        float* __restrict__ C0, const float* __restrict__ B1,
                        float* __restrict__ C1, int M, int N, int K) {
    constexpr int BM = 128, BK = 32;
    constexpr int BNS = BN + 8;
    constexpr int ASZ = BM * BK;       // floats per A stage
    constexpr int BSZ = BK * BNS;      // floats per B stage
    constexpr int NT = BN / 16;        // n-tiles per warp
    constexpr int BG = BN / 4;         // float4 groups per B row

    extern __shared__ float sm[];
    const int tid = threadIdx.x;
    const int warp = tid >> 5, lane = tid & 31;
    const int gid = lane >> 2, tig = lane & 3;
    const int wm = warp >> 1, wn = warp & 1;

    const float* Bg;
    float* C;
    int bn;
    if (KV) {
        Bg = blockIdx.x ? B1 : B0;
        C = blockIdx.x ? C1 : C0;
        bn = 0;
    } else {
        Bg = B0;
        C = C0;
        bn = blockIdx.x * BN;
    }
    const int bm = blockIdx.y * BM;

    uint32_t sbase = (uint32_t)__cvta_generic_to_shared(sm);

    auto ld_stage = [&](int stage, int k0) {
        uint32_t abase = sbase + stage * ASZ * 4;
        uint32_t bbase = sbase + (2 * ASZ + stage * BSZ) * 4;
#pragma unroll
        for (int t = tid; t < BM * 8; t += 256) {
            int m = t >> 3, g = t & 7;
            int col = (g * 4) ^ ((m & 7) * 4);
            CPA16(abase + (m * 32 + col) * 4, A + (size_t)(bm + m) * K + k0 + g * 4);
        }
#pragma unroll
        for (int t = tid; t < BK * BG; t += 256) {
            int k = t / BG, g = t % BG;
            CPA16(bbase + (k * BNS + g * 4) * 4, Bg + (size_t)(k0 + k) * N + bn + g * 4);
        }
    };

    float acc[2][NT][4];
#pragma unroll
    for (int mt = 0; mt < 2; mt++)
#pragma unroll
        for (int nt = 0; nt < NT; nt++)
#pragma unroll
            for (int c = 0; c < 4; c++) acc[mt][nt][c] = 0.0f;

    const int nk = K / BK;
    ld_stage(0, 0);
    asm volatile("cp.async.commit_group;");

    int buf = 0;
    for (int kt = 0; kt < nk; kt++) {
        if (kt + 1 < nk) {
            ld_stage(buf ^ 1, (kt + 1) * BK);
            asm volatile("cp.async.commit_group;");
            asm volatile("cp.async.wait_group 1;");
        } else {
            asm volatile("cp.async.wait_group 0;");
        }
        __syncthreads();

        const float* As = sm + buf * ASZ;
        const float* Bs = sm + 2 * ASZ + buf * BSZ;
#pragma unroll
        for (int ks = 0; ks < 4; ks++) {
            unsigned a[2][4];
#pragma unroll
            for (int mt = 0; mt < 2; mt++) {
                int m = wm * 32 + mt * 16 + gid;
                int sw = (m & 7) * 4;
                int k0c = ks * 8 + tig;
                a[mt][0] = f2tf(As[m * 32 + (k0c ^ sw)]);
                a[mt][1] = f2tf(As[(m + 8) * 32 + (k0c ^ sw)]);
                a[mt][2] = f2tf(As[m * 32 + ((k0c + 4) ^ sw)]);
                a[mt][3] = f2tf(As[(m + 8) * 32 + ((k0c + 4) ^ sw)]);
            }
#pragma unroll
            for (int nt = 0; nt < NT; nt++) {
                int n = wn * (BN / 2) + nt * 8 + gid;
                unsigned bb[2];
                bb[0] = f2tf(Bs[(ks * 8 + tig) * BNS + n]);
                bb[1] = f2tf(Bs[(ks * 8 + tig + 4) * BNS + n]);
                mma8(acc[0][nt], a[0], bb);
                mma8(acc[1][nt], a[1], bb);
            }
        }
        __syncthreads();
        buf ^= 1;
    }

#pragma unroll
    for (int mt = 0; mt < 2; mt++) {
        int row = bm + wm * 32 + mt * 16 + gid;
#pragma unroll
        for (int nt = 0; nt < NT; nt++) {
            int col = bn + wn * (BN / 2) + nt * 8 + tig * 2;
            *(float2*)&C[(size_t)row * N + col] = make_float2(acc[mt][nt][0], acc[mt][nt][1]);
            *(float2*)&C[(size_t)(row + 8) * N + col] = make_float2(acc[mt][nt][2], acc[mt][nt][3]);
        }
    }
}

// ---------------- RoPE (in-place) ----------------
__global__ void rope_kernel(float* __restrict__ q, float* __restrict__ k) {
    const long total = (long)B * S * (H + 1) * 32;
    long gtid = (long)blockIdx.x * blockDim.x + threadIdx.x;
    if (gtid >= total) return;
    int lane = (int)(gtid & 31);
    long chunk = gtid >> 5;
    const long nq = (long)B * S * H;

    float* base;
    int s;
    if (chunk < nq) {
        s = (int)((chunk / H) % S);
        base = q + chunk * 64;
    } else {
        long c2 = chunk - nq;
        s = (int)(c2 % S);
        base = k + c2 * 64;
    }
    float freq = powf(1000.0f, -(float)lane / 32.0f);
    float ang = (float)s * freq;
    float sn, cs;
    sincosf(ang, &sn, &cs);
    float t0 = base[2 * lane];
    float t1 = base[2 * lane + 1];
    __syncwarp();
    base[lane] = t0 * cs - t1 * sn;
    base[lane + 32] = t1 * cs + t0 * sn;
}

// ---------------- tf32 flash attention (causal, MQA) ----------------
// grid (S/64, H, B), 128 threads = 4 warps, each warp = 16 query rows.
// smem: Qs[64][72], Kt[64][72] (d x ki), Vs[64][72] (ki x d), Ps[64][72]
__global__ void attn_tc(const float* __restrict__ q, const float* __restrict__ k,
                        const float* __restrict__ v, float* __restrict__ o) {
    constexpr int ST = 72;
    extern __shared__ float sm[];
    float* Qs = sm;
    float* Kt = sm + 64 * ST;
    float* Vs = sm + 2 * 64 * ST;
    float* Ps = sm + 3 * 64 * ST;

    const int qt = gridDim.x - 1 - blockIdx.x;  // big tiles first
    const int h = blockIdx.y, b = blockIdx.z;
    const int tid = threadIdx.x;
    const int warp = tid >> 5, lane = tid & 31;
    const int gid = lane >> 2, tig = lane & 3;
    const int qbase = qt * 64;
    const float scale = 0.125f;

    // load Q tile (scaled)
    for (int t = tid; t < 64 * 16; t += 128) {
        int r = t >> 4, g = t & 15;
        float4 qv = *(const float4*)&q[((size_t)b * S + qbase + r) * D + h * 64 + g * 4];
        qv.x *= scale; qv.y *= scale; qv.z *= scale; qv.w *= scale;
        *(float4*)&Qs[r * ST + g * 4] = qv;
    }

    float m0 = -1e30f, m1 = -1e30f, l0 = 0.0f, l1 = 0.0f;
    float acc[8][4];
#pragma unroll
    for (int nt = 0; nt < 8; nt++)
#pragma unroll
        for (int c = 0; c < 4; c++) acc[nt][c] = 0.0f;

    const int r = warp * 16 + gid;

    for (int kt = 0; kt <= qt; kt++) {
        __syncthreads();
        const int kvbase = kt * 64;
        for (int t = tid; t < 64 * 16; t += 128) {
            int ki = t >> 4, g = t & 15;
            float4 kv4 = *(const float4*)&k[((size_t)b * S + kvbase + ki) * HD + g * 4];
            Kt[(g * 4 + 0) * ST + ki] = kv4.x;
            Kt[(g * 4 + 1) * ST + ki] = kv4.y;
            Kt[(g * 4 + 2) * ST + ki] = kv4.z;
            Kt[(g * 4 + 3) * ST + ki] = kv4.w;
            float4 vv4 = *(const float4*)&v[((size_t)b * S + kvbase + ki) * HD + g * 4];
            *(float4*)&Vs[ki * ST + g * 4] = vv4;
        }
        __syncthreads();

        // S = Q K^T
        float sv[8][4];
#pragma unroll
        for (int nt = 0; nt < 8; nt++)
#pragma unroll
            for (int c = 0; c < 4; c++) sv[nt][c] = 0.0f;
#pragma unroll
        for (int ks = 0; ks < 8; ks++) {
            unsigned a[4];
            a[0] = f2tf(Qs[r * ST + ks * 8 + tig]);
            a[1] = f2tf(Qs[(r + 8) * ST + ks * 8 + tig]);
            a[2] = f2tf(Qs[r * ST + ks * 8 + tig + 4]);
            a[3] = f2tf(Qs[(r + 8) * ST + ks * 8 + tig + 4]);
#pragma unroll
            for (int nt = 0; nt < 8; nt++) {
                unsigned bb[2];
                bb[0] = f2tf(Kt[(ks * 8 + tig) * ST + nt * 8 + gid]);
                bb[1] = f2tf(Kt[(ks * 8 + tig + 4) * ST + nt * 8 + gid]);
                mma8(sv[nt], a, bb);
            }
        }

        // causal mask on the diagonal tile
        if (kt == qt) {
            int gr0 = qbase + r, gr1 = gr0 + 8;
#pragma unroll
            for (int nt = 0; nt < 8; nt++) {
                int col = kvbase + nt * 8 + tig * 2;
                if (col > gr0) sv[nt][0] = -1e30f;
                if (col + 1 > gr0) sv[nt][1] = -1e30f;
                if (col > gr1) sv[nt][2] = -1e30f;
                if (col + 1 > gr1) sv[nt][3] = -1e30f;
            }
        }

        // online softmax
        float rm0 = -1e30f, rm1 = -1e30f;
#pragma unroll
        for (int nt = 0; nt < 8; nt++) {
            rm0 = fmaxf(rm0, fmaxf(sv[nt][0], sv[nt][1]));
            rm1 = fmaxf(rm1, fmaxf(sv[nt][2], sv[nt][3]));
        }
        rm0 = fmaxf(rm0, __shfl_xor_sync(0xffffffffu, rm0, 1));
        rm0 = fmaxf(rm0, __shfl_xor_sync(0xffffffffu, rm0, 2));
        rm1 = fmaxf(rm1, __shfl_xor_sync(0xffffffffu, rm1, 1));
        rm1 = fmaxf(rm1, __shfl_xor_sync(0xffffffffu, rm1, 2));

        float mn0 = fmaxf(m0, rm0), mn1 = fmaxf(m1, rm1);
        float al0 = __expf(m0 - mn0), al1 = __expf(m1 - mn1);
        float rs0 = 0.0f, rs1 = 0.0f;
#pragma unroll
        for (int nt = 0; nt < 8; nt++) {
            float p0 = __expf(sv[nt][0] - mn0);
            float p1 = __expf(sv[nt][1] - mn0);
            float p2 = __expf(sv[nt][2] - mn1);
            float p3 = __expf(sv[nt][3] - mn1);
            rs0 += p0 + p1;
            rs1 += p2 + p3;
            int col = nt * 8 + tig * 2;
            Ps[r * ST + col] = p0;
            Ps[r * ST + col + 1] = p1;
            Ps[(r + 8) * ST + col] = p2;
            Ps[(r + 8) * ST + col + 1] = p3;
        }
        rs0 += __shfl_xor_sync(0xffffffffu, rs0, 1);
        rs0 += __shfl_xor_sync(0xffffffffu, rs0, 2);
        rs1 += __shfl_xor_sync(0xffffffffu, rs1, 1);
        rs1 += __shfl_xor_sync(0xffffffffu, rs1, 2);
        l0 = l0 * al0 + rs0;
        l1 = l1 * al1 + rs1;
        m0 = mn0;
        m1 = mn1;
#pragma unroll
        for (int nt = 0; nt < 8; nt++) {
            acc[nt][0] *= al0;
            acc[nt][1] *= al0;
            acc[nt][2] *= al1;
            acc[nt][3] *= al1;
        }
        __syncwarp();

        // O += P V
#pragma unroll
        for (int ks = 0; ks < 8; ks++) {
            unsigned a[4];
            a[0] = f2tf(Ps[r * ST + ks * 8 + tig]);
            a[1] = f2tf(Ps[(r + 8) * ST + ks * 8 + tig]);
            a[2] = f2tf(Ps[r * ST + ks * 8 + tig + 4]);
            a[3] = f2tf(Ps[(r + 8) * ST + ks * 8 + tig + 4]);
#pragma unroll
            for (int nt = 0; nt < 8; nt++) {
                unsigned bb[2];
                bb[0] = f2tf(Vs[(ks * 8 + tig) * ST + nt * 8 + gid]);
                bb[1] = f2tf(Vs[(ks * 8 + tig + 4) * ST + nt * 8 + gid]);
                mma8(acc[nt], a, bb);
            }
        }
    }

    float inv0 = 1.0f / l0, inv1 = 1.0f / l1;
#pragma unroll
    for (int nt = 0; nt < 8; nt++) {
        int col = h * 64 + nt * 8 + tig * 2;
        *(float2*)&o[((size_t)b * S + qbase + r) * D + col] =
            make_float2(acc[nt][0] * inv0, acc[nt][1] * inv0);
        *(float2*)&o[((size_t)b * S + qbase + r + 8) * D + col] =
            make_float2(acc[nt][2] * inv1, acc[nt][3] * inv1);
    }
}

// ---------------- launch ----------------
extern "C" void kernel_launch(void* const* d_in, const int* in_sizes, int n_in,
                              void* d_out, int out_size) {
    const float* x = (const float*)d_in[0];
    const float* wq = (const float*)d_in[1];
    const float* wk = (const float*)d_in[2];
    const float* wv = (const float*)d_in[3];
    const float* wo = (const float*)d_in[4];
    float* out = (float*)d_out;

    float *qp, *kp, *vp, *ap, *wqt, *wot;
    cudaGetSymbolAddress((void**)&qp, g_q);
    cudaGetSymbolAddress((void**)&kp, g_k);
    cudaGetSymbolAddress((void**)&vp, g_v);
    cudaGetSymbolAddress((void**)&ap, g_att);
    cudaGetSymbolAddress((void**)&wqt, g_wqt);
    cudaGetSymbolAddress((void**)&wot, g_wot);

    const int M = B * S;  // 4096
    const int SM128 = (2 * 128 * 32 + 2 * 32 * 136) * 4;  // 67584
    const int SM64 = (2 * 128 * 32 + 2 * 32 * 72) * 4;    // 51200
    const int SMATT = 4 * 64 * 72 * 4;                    // 73728

    cudaFuncSetAttribute(gemm_tc<128, false>, cudaFuncAttributeMaxDynamicSharedMemorySize, SM128);
    cudaFuncSetAttribute(gemm_tc<64, true>, cudaFuncAttributeMaxDynamicSharedMemorySize, SM64);
    cudaFuncSetAttribute(attn_tc, cudaFuncAttributeMaxDynamicSharedMemorySize, SMATT);

    // transpose wq, wo
    tr1024<<<dim3(32, 32, 2), dim3(32, 8)>>>(wq, wo, wqt, wot);

    // Q = x @ wq^T
    gemm_tc<128, false><<<dim3(D / 128, M / 128), 256, SM128>>>(x, wqt, qp, nullptr, nullptr, M, D, D);
    // K = x @ wk, V = x @ wv (dual)
    gemm_tc<64, true><<<dim3(2, M / 128), 256, SM64>>>(x, wk, kp, wv, vp, M, HD, D);

    // RoPE
    {
        long total = (long)B * S * (H + 1) * 32;
        rope_kernel<<<(unsigned)((total + 255) / 256), 256>>>(qp, kp);
    }

    // attention
    attn_tc<<<dim3(S / 64, H, B), 128, SMATT>>>(qp, kp, vp, ap);

    // out = att @ wo^T
    gemm_tc<128, false><<<dim3(D / 128, M / 128), 256, SM128>>>(ap, wot, out, nullptr, nullptr, M, D, D);
}

// round 4
// speedup vs baseline: 3.3295x; 1.1734x over previous
#include <cuda_runtime.h>
#include <math.h>
#include <stdint.h>

#define B 2
#define S 2048
#define D 1024
#define H 16
#define HD 64

// ---------------- scratch (allocation-free) ----------------
__device__ float g_q[B * S * D];      // 16 MB
__device__ float g_k[B * S * HD];     // 1 MB
__device__ float g_v[B * S * HD];     // 1 MB
__device__ float g_att[B * S * D];    // 16 MB
__device__ float g_x[B * S * D];      // 16 MB  tf32-rounded x
__device__ float g_wqt[D * D];        // 4 MB   wq^T (tf32)
__device__ float g_wot[D * D];        // 4 MB   wo^T (tf32)
__device__ float g_wk2[D * HD];       // 256 KB wk (tf32)
__device__ float g_wv2[D * HD];       // 256 KB wv (tf32)

// ---------------- helpers ----------------
__device__ __forceinline__ unsigned f2tf(float x) {
    unsigned r;
    asm("cvt.rna.tf32.f32 %0, %1;" : "=r"(r) : "f"(x));
    return r;
}
__device__ __forceinline__ float f2tff(float x) { return __uint_as_float(f2tf(x)); }

__device__ __forceinline__ void mma8(float* c, const unsigned* a, const unsigned* b) {
    asm volatile(
        "mma.sync.aligned.m16n8k8.row.col.f32.tf32.tf32.f32 "
        "{%0,%1,%2,%3}, {%4,%5,%6,%7}, {%8,%9}, {%0,%1,%2,%3};"
        : "+f"(c[0]), "+f"(c[1]), "+f"(c[2]), "+f"(c[3])
        : "r"(a[0]), "r"(a[1]), "r"(a[2]), "r"(a[3]), "r"(b[0]), "r"(b[1]));
}
// raw-load variant: operands already tf32-rounded in smem
__device__ __forceinline__ void mma8f(float* c, const float* a, const float* b) {
    unsigned au[4] = {__float_as_uint(a[0]), __float_as_uint(a[1]),
                      __float_as_uint(a[2]), __float_as_uint(a[3])};
    unsigned bu[2] = {__float_as_uint(b[0]), __float_as_uint(b[1])};
    mma8(c, au, bu);
}

#define CPA16(dst, src) \
    asm volatile("cp.async.cg.shared.global [%0], [%1], 16;" ::"r"(dst), "l"(src))

// ---------------- elementwise tf32 rounding ----------------
__global__ void cvt_x(const float* __restrict__ in, float* __restrict__ out, int n4) {
    int i = blockIdx.x * blockDim.x + threadIdx.x;
    if (i >= n4) return;
    float4 v = ((const float4*)in)[i];
    v.x = f2tff(v.x); v.y = f2tff(v.y); v.z = f2tff(v.z); v.w = f2tff(v.w);
    ((float4*)out)[i] = v;
}
__global__ void cvt_wkv(const float* __restrict__ wk, const float* __restrict__ wv,
                        float* __restrict__ ok, float* __restrict__ ov) {
    int i = blockIdx.x * blockDim.x + threadIdx.x;  // 32768 float4s total
    const float* in = (i < 16384) ? wk : wv;
    float* out = (i < 16384) ? ok : ov;
    int j = (i < 16384) ? i : i - 16384;
    float4 v = ((const float4*)in)[j];
    v.x = f2tff(v.x); v.y = f2tff(v.y); v.z = f2tff(v.z); v.w = f2tff(v.w);
    ((float4*)out)[j] = v;
}

// ---------------- 1024x1024 transpose + tf32 round (wq, wo) ----------------
__global__ void tr1024(const float* __restrict__ a, const float* __restrict__ b,
                       float* __restrict__ ta, float* __restrict__ tb) {
    const float* in = blockIdx.z ? b : a;
    float* out = blockIdx.z ? tb : ta;
    __shared__ float t[32][33];
    int x = blockIdx.x * 32 + threadIdx.x;
    int y0 = blockIdx.y * 32;
    for (int i = threadIdx.y; i < 32; i += 8)
        t[i][threadIdx.x] = in[(y0 + i) * 1024 + x];
    __syncthreads();
    int x2 = y0 + threadIdx.x;
    int y2 = blockIdx.x * 32;
    for (int i = threadIdx.y; i < 32; i += 8)
        out[(y2 + i) * 1024 + x2] = f2tff(t[threadIdx.x][i]);
}

// ---------------- tf32 tensor-core GEMM (operands pre-rounded) ----------------
// C[M,N] = A[M,K] * Bg[K,N]. BM=128, BK=32. 256 threads = 8 warps (4m x 2n).
template <int BN, bool KV, bool CVTOUT>
__global__ void gemm_tc(const float* __restrict__ A, const float* __restrict__ B0,
                        float* __restrict__ C0, const float* __restrict__ B1,
                        float* __restrict__ C1, int M, int N, int K) {
    constexpr int BM = 128, BK = 32;
    constexpr int BNS = BN + 8;
    constexpr int ASZ = BM * BK;
    constexpr int BSZ = BK * BNS;
    constexpr int NT = BN / 16;
    constexpr int BG = BN / 4;

    extern __shared__ float sm[];
    const int tid = threadIdx.x;
    const int warp = tid >> 5, lane = tid & 31;
    const int gid = lane >> 2, tig = lane & 3;
    const int wm = warp >> 1, wn = warp & 1;

    const float* Bg;
    float* C;
    int bn;
    if (KV) {
        Bg = blockIdx.x ? B1 : B0;
        C = blockIdx.x ? C1 : C0;
        bn = 0;
    } else {
        Bg = B0;
        C = C0;
        bn = blockIdx.x * BN;
    }
    const int bm = blockIdx.y * BM;

    uint32_t sbase = (uint32_t)__cvta_generic_to_shared(sm);

    auto ld_stage = [&](int stage, int k0) {
        uint32_t abase = sbase + stage * ASZ * 4;
        uint32_t bbase = sbase + (2 * ASZ + stage * BSZ) * 4;
#pragma unroll
        for (int t = tid; t < BM * 8; t += 256) {
            int m = t >> 3, g = t & 7;
            int col = (g * 4) ^ ((m & 7) * 4);
            CPA16(abase + (m * 32 + col) * 4, A + (size_t)(bm + m) * K + k0 + g * 4);
        }
#pragma unroll
        for (int t = tid; t < BK * BG; t += 256) {
            int k = t / BG, g = t % BG;
            CPA16(bbase + (k * BNS + g * 4) * 4, Bg + (size_t)(k0 + k) * N + bn + g * 4);
        }
    };

    float acc[2][NT][4];
#pragma unroll
    for (int mt = 0; mt < 2; mt++)
#pragma unroll
        for (int nt = 0; nt < NT; nt++)
#pragma unroll
            for (int c = 0; c < 4; c++) acc[mt][nt][c] = 0.0f;

    const int nk = K / BK;
    ld_stage(0, 0);
    asm volatile("cp.async.commit_group;");

    int buf = 0;
    for (int kt = 0; kt < nk; kt++) {
        if (kt + 1 < nk) {
            ld_stage(buf ^ 1, (kt + 1) * BK);
            asm volatile("cp.async.commit_group;");
            asm volatile("cp.async.wait_group 1;");
        } else {
            asm volatile("cp.async.wait_group 0;");
        }
        __syncthreads();

        const float* As = sm + buf * ASZ;
        const float* Bs = sm + 2 * ASZ + buf * BSZ;
#pragma unroll
        for (int ks = 0; ks < 4; ks++) {
            float a[2][4];
#pragma unroll
            for (int mt = 0; mt < 2; mt++) {
                int m = wm * 32 + mt * 16 + gid;
                int sw = (m & 7) * 4;
                int k0c = ks * 8 + tig;
                a[mt][0] = As[m * 32 + (k0c ^ sw)];
                a[mt][1] = As[(m + 8) * 32 + (k0c ^ sw)];
                a[mt][2] = As[m * 32 + ((k0c + 4) ^ sw)];
                a[mt][3] = As[(m + 8) * 32 + ((k0c + 4) ^ sw)];
            }
#pragma unroll
            for (int nt = 0; nt < NT; nt++) {
                int n = wn * (BN / 2) + nt * 8 + gid;
                float bb[2];
                bb[0] = Bs[(ks * 8 + tig) * BNS + n];
                bb[1] = Bs[(ks * 8 + tig + 4) * BNS + n];
                mma8f(acc[0][nt], a[0], bb);
                mma8f(acc[1][nt], a[1], bb);
            }
        }
        __syncthreads();
        buf ^= 1;
    }

#pragma unroll
    for (int mt = 0; mt < 2; mt++) {
        int row = bm + wm * 32 + mt * 16 + gid;
#pragma unroll
        for (int nt = 0; nt < NT; nt++) {
            int col = bn + wn * (BN / 2) + nt * 8 + tig * 2;
            float o0 = acc[mt][nt][0], o1 = acc[mt][nt][1];
            float o2 = acc[mt][nt][2], o3 = acc[mt][nt][3];
            if (CVTOUT) { o0 = f2tff(o0); o1 = f2tff(o1); o2 = f2tff(o2); o3 = f2tff(o3); }
            *(float2*)&C[(size_t)row * N + col] = make_float2(o0, o1);
            *(float2*)&C[(size_t)(row + 8) * N + col] = make_float2(o2, o3);
        }
    }
}

// ---------------- RoPE (in-place, outputs tf32-rounded) ----------------
__global__ void rope_kernel(float* __restrict__ q, float* __restrict__ k) {
    const long total = (long)B * S * (H + 1) * 32;
    long gtid = (long)blockIdx.x * blockDim.x + threadIdx.x;
    if (gtid >= total) return;
    int lane = (int)(gtid & 31);
    long chunk = gtid >> 5;
    const long nq = (long)B * S * H;

    float* base;
    int s;
    if (chunk < nq) {
        s = (int)((chunk / H) % S);
        base = q + chunk * 64;
    } else {
        long c2 = chunk - nq;
        s = (int)(c2 % S);
        base = k + c2 * 64;
    }
    float freq = powf(1000.0f, -(float)lane / 32.0f);
    float ang = (float)s * freq;
    float sn, cs;
    sincosf(ang, &sn, &cs);
    float t0 = base[2 * lane];
    float t1 = base[2 * lane + 1];
    __syncwarp();
    base[lane] = f2tff(t0 * cs - t1 * sn);
    base[lane + 32] = f2tff(t1 * cs + t0 * sn);
}

// ---------------- tf32 flash attention (causal, MQA) ----------------
// BQ=128 queries/block, 8 warps (16 rows each). kt tiles of 64 keys.
// smem: Qs[128][72], Ps[128][72], Kt[64][72], Vs[64][72] = 110592 B
__global__ void __launch_bounds__(256, 2)
attn_tc(const float* __restrict__ q, const float* __restrict__ k,
        const float* __restrict__ v, float* __restrict__ o) {
    constexpr int ST = 72;
    extern __shared__ float sm[];
    float* Qs = sm;                 // [128][ST]
    float* Ps = sm + 128 * ST;      // [128][ST]
    float* Kt = sm + 256 * ST;      // [64][ST]  (d x ki)
    float* Vs = sm + 256 * ST + 64 * ST;  // [64][ST] (ki x d)

    const int qt = gridDim.x - 1 - blockIdx.x;  // deep tiles first
    const int h = blockIdx.y, b = blockIdx.z;
    const int tid = threadIdx.x;
    const int warp = tid >> 5, lane = tid & 31;
    const int gid = lane >> 2, tig = lane & 3;
    const int qbase = qt * 128;
    const float scale = 0.125f;  // exact power of 2: keeps tf32 rounding

    for (int t = tid; t < 128 * 16; t += 256) {
        int r = t >> 4, g = t & 15;
        float4 qv = *(const float4*)&q[((size_t)b * S + qbase + r) * D + h * 64 + g * 4];
        qv.x *= scale; qv.y *= scale; qv.z *= scale; qv.w *= scale;
        *(float4*)&Qs[r * ST + g * 4] = qv;
    }

    float m0 = -1e30f, m1 = -1e30f, l0 = 0.0f, l1 = 0.0f;
    float acc[8][4];
#pragma unroll
    for (int nt = 0; nt < 8; nt++)
#pragma unroll
        for (int c = 0; c < 4; c++) acc[nt][c] = 0.0f;

    const int r = warp * 16 + gid;
    const int nkt = qt * 2 + 2;

    for (int kt = 0; kt < nkt; kt++) {
        __syncthreads();
        const int kvbase = kt * 64;
        for (int t = tid; t < 64 * 16; t += 256) {
            int ki = t >> 4, g = t & 15;
            float4 kv4 = *(const float4*)&k[((size_t)b * S + kvbase + ki) * HD + g * 4];
            Kt[(g * 4 + 0) * ST + ki] = kv4.x;
            Kt[(g * 4 + 1) * ST + ki] = kv4.y;
            Kt[(g * 4 + 2) * ST + ki] = kv4.z;
            Kt[(g * 4 + 3) * ST + ki] = kv4.w;
            float4 vv4 = *(const float4*)&v[((size_t)b * S + kvbase + ki) * HD + g * 4];
            *(float4*)&Vs[ki * ST + g * 4] = vv4;
        }
        __syncthreads();

        // S = Q K^T (raw loads; operands pre-rounded)
        float sv[8][4];
#pragma unroll
        for (int nt = 0; nt < 8; nt++)
#pragma unroll
            for (int c = 0; c < 4; c++) sv[nt][c] = 0.0f;
#pragma unroll
        for (int ks = 0; ks < 8; ks++) {
            float a[4];
            a[0] = Qs[r * ST + ks * 8 + tig];
            a[1] = Qs[(r + 8) * ST + ks * 8 + tig];
            a[2] = Qs[r * ST + ks * 8 + tig + 4];
            a[3] = Qs[(r + 8) * ST + ks * 8 + tig + 4];
#pragma unroll
            for (int nt = 0; nt < 8; nt++) {
                float bb[2];
                bb[0] = Kt[(ks * 8 + tig) * ST + nt * 8 + gid];
                bb[1] = Kt[(ks * 8 + tig + 4) * ST + nt * 8 + gid];
                mma8f(sv[nt], a, bb);
            }
        }

        // causal mask: only last two kt tiles can cross the diagonal
        if (kt >= nkt - 2) {
            int gr0 = qbase + r, gr1 = gr0 + 8;
#pragma unroll
            for (int nt = 0; nt < 8; nt++) {
                int col = kvbase + nt * 8 + tig * 2;
                if (col > gr0) sv[nt][0] = -1e30f;
                if (col + 1 > gr0) sv[nt][1] = -1e30f;
                if (col > gr1) sv[nt][2] = -1e30f;
                if (col + 1 > gr1) sv[nt][3] = -1e30f;
            }
        }

        // online softmax
        float rm0 = -1e30f, rm1 = -1e30f;
#pragma unroll
        for (int nt = 0; nt < 8; nt++) {
            rm0 = fmaxf(rm0, fmaxf(sv[nt][0], sv[nt][1]));
            rm1 = fmaxf(rm1, fmaxf(sv[nt][2], sv[nt][3]));
        }
        rm0 = fmaxf(rm0, __shfl_xor_sync(0xffffffffu, rm0, 1));
        rm0 = fmaxf(rm0, __shfl_xor_sync(0xffffffffu, rm0, 2));
        rm1 = fmaxf(rm1, __shfl_xor_sync(0xffffffffu, rm1, 1));
        rm1 = fmaxf(rm1, __shfl_xor_sync(0xffffffffu, rm1, 2));

        float mn0 = fmaxf(m0, rm0), mn1 = fmaxf(m1, rm1);
        float al0 = __expf(m0 - mn0), al1 = __expf(m1 - mn1);
        float rs0 = 0.0f, rs1 = 0.0f;
#pragma unroll
        for (int nt = 0; nt < 8; nt++) {
            float p0 = __expf(sv[nt][0] - mn0);
            float p1 = __expf(sv[nt][1] - mn0);
            float p2 = __expf(sv[nt][2] - mn1);
            float p3 = __expf(sv[nt][3] - mn1);
            rs0 += p0 + p1;
            rs1 += p2 + p3;
            int col = nt * 8 + tig * 2;
            Ps[r * ST + col] = f2tff(p0);
            Ps[r * ST + col + 1] = f2tff(p1);
            Ps[(r + 8) * ST + col] = f2tff(p2);
            Ps[(r + 8) * ST + col + 1] = f2tff(p3);
        }
        rs0 += __shfl_xor_sync(0xffffffffu, rs0, 1);
        rs0 += __shfl_xor_sync(0xffffffffu, rs0, 2);
        rs1 += __shfl_xor_sync(0xffffffffu, rs1, 1);
        rs1 += __shfl_xor_sync(0xffffffffu, rs1, 2);
        l0 = l0 * al0 + rs0;
        l1 = l1 * al1 + rs1;
        m0 = mn0;
        m1 = mn1;
#pragma unroll
        for (int nt = 0; nt < 8; nt++) {
            acc[nt][0] *= al0;
            acc[nt][1] *= al0;
            acc[nt][2] *= al1;
            acc[nt][3] *= al1;
        }
        __syncwarp();

        // O += P V (raw loads)
#pragma unroll
        for (int ks = 0; ks < 8; ks++) {
            float a[4];
            a[0] = Ps[r * ST + ks * 8 + tig];
            a[1] = Ps[(r + 8) * ST + ks * 8 + tig];
            a[2] = Ps[r * ST + ks * 8 + tig + 4];
            a[3] = Ps[(r + 8) * ST + ks * 8 + tig + 4];
#pragma unroll
            for (int nt = 0; nt < 8; nt++) {
                float bb[2];
                bb[0] = Vs[(ks * 8 + tig) * ST + nt * 8 + gid];
                bb[1] = Vs[(ks * 8 + tig + 4) * ST + nt * 8 + gid];
                mma8f(acc[nt], a, bb);
            }
        }
    }

    float inv0 = 1.0f / l0, inv1 = 1.0f / l1;
#pragma unroll
    for (int nt = 0; nt < 8; nt++) {
        int col = h * 64 + nt * 8 + tig * 2;
        *(float2*)&o[((size_t)b * S + qbase + r) * D + col] =
            make_float2(f2tff(acc[nt][0] * inv0), f2tff(acc[nt][1] * inv0));
        *(float2*)&o[((size_t)b * S + qbase + r + 8) * D + col] =
            make_float2(f2tff(acc[nt][2] * inv1), f2tff(acc[nt][3] * inv1));
    }
}

// ---------------- launch ----------------
extern "C" void kernel_launch(void* const* d_in, const int* in_sizes, int n_in,
                              void* d_out, int out_size) {
    const float* x = (const float*)d_in[0];
    const float* wq = (const float*)d_in[1];
    const float* wk = (const float*)d_in[2];
    const float* wv = (const float*)d_in[3];
    const float* wo = (const float*)d_in[4];
    float* out = (float*)d_out;

    float *qp, *kp, *vp, *ap, *xp, *wqt, *wot, *wkp, *wvp;
    cudaGetSymbolAddress((void**)&qp, g_q);
    cudaGetSymbolAddress((void**)&kp, g_k);
    cudaGetSymbolAddress((void**)&vp, g_v);
    cudaGetSymbolAddress((void**)&ap, g_att);
    cudaGetSymbolAddress((void**)&xp, g_x);
    cudaGetSymbolAddress((void**)&wqt, g_wqt);
    cudaGetSymbolAddress((void**)&wot, g_wot);
    cudaGetSymbolAddress((void**)&wkp, g_wk2);
    cudaGetSymbolAddress((void**)&wvp, g_wv2);

    const int M = B * S;  // 4096
    const int SM128 = (2 * 128 * 32 + 2 * 32 * 136) * 4;  // 67584
    const int SM64 = (2 * 128 * 32 + 2 * 32 * 72) * 4;    // 51200
    const int SMATT = (2 * 128 + 2 * 64) * 72 * 4;        // 110592

    cudaFuncSetAttribute(gemm_tc<128, false, false>, cudaFuncAttributeMaxDynamicSharedMemorySize, SM128);
    cudaFuncSetAttribute(gemm_tc<64, true, true>, cudaFuncAttributeMaxDynamicSharedMemorySize, SM64);
    cudaFuncSetAttribute(attn_tc, cudaFuncAttributeMaxDynamicSharedMemorySize, SMATT);

    // pre-round inputs to tf32
    cvt_x<<<(M * D / 4 + 255) / 256, 256>>>(x, xp, M * D / 4);
    cvt_wkv<<<(2 * D * HD / 4 + 255) / 256, 256>>>(wk, wv, wkp, wvp);
    tr1024<<<dim3(32, 32, 2), dim3(32, 8)>>>(wq, wo, wqt, wot);

    // Q = x @ wq^T
    gemm_tc<128, false, false><<<dim3(D / 128, M / 128), 256, SM128>>>(xp, wqt, qp, nullptr, nullptr, M, D, D);
    // K = x @ wk, V = x @ wv (dual; outputs tf32-rounded)
    gemm_tc<64, true, true><<<dim3(2, M / 128), 256, SM64>>>(xp, wkp, kp, wvp, vp, M, HD, D);

    // RoPE (outputs tf32-rounded)
    {
        long total = (long)B * S * (H + 1) * 32;
        rope_kernel<<<(unsigned)((total + 255) / 256), 256>>>(qp, kp);
    }

    // attention (output tf32-rounded for O-proj)
    attn_tc<<<dim3(S / 128, H, B), 256, SMATT>>>(qp, kp, vp, ap);

    // out = att @ wo^T (final: no rounding)
    gemm_tc<128, false, false><<<dim3(D / 128, M / 128), 256, SM128>>>(ap, wot, out, nullptr, nullptr, M, D, D);
}

// round 5
// speedup vs baseline: 4.5235x; 1.3586x over previous
#include <cuda_runtime.h>
#include <math.h>
#include <stdint.h>

#define B 2
#define S 2048
#define D 1024
#define H 16
#define HD 64

// ---------------- scratch (allocation-free) ----------------
__device__ float g_q[B * S * D];      // 16 MB
__device__ float g_k[B * S * HD];     // 1 MB
__device__ float g_kt[B * HD * S];    // 1 MB   K transposed [b][d][s]
__device__ float g_v[B * S * HD];     // 1 MB
__device__ float g_att[B * S * D];    // 16 MB
__device__ float g_x[B * S * D];      // 16 MB  tf32-rounded x
__device__ float g_wqt[D * D];        // 4 MB   wq^T (tf32)
__device__ float g_wot[D * D];        // 4 MB   wo^T (tf32)
__device__ float g_wk2[D * HD];       // 256 KB wk (tf32)
__device__ float g_wv2[D * HD];       // 256 KB wv (tf32)

// ---------------- helpers ----------------
__device__ __forceinline__ unsigned f2tf(float x) {
    unsigned r;
    asm("cvt.rna.tf32.f32 %0, %1;" : "=r"(r) : "f"(x));
    return r;
}
__device__ __forceinline__ float f2tff(float x) { return __uint_as_float(f2tf(x)); }

__device__ __forceinline__ void mma8(float* c, const unsigned* a, const unsigned* b) {
    asm volatile(
        "mma.sync.aligned.m16n8k8.row.col.f32.tf32.tf32.f32 "
        "{%0,%1,%2,%3}, {%4,%5,%6,%7}, {%8,%9}, {%0,%1,%2,%3};"
        : "+f"(c[0]), "+f"(c[1]), "+f"(c[2]), "+f"(c[3])
        : "r"(a[0]), "r"(a[1]), "r"(a[2]), "r"(a[3]), "r"(b[0]), "r"(b[1]));
}
__device__ __forceinline__ void mma8f(float* c, const float* a, const float* b) {
    unsigned au[4] = {__float_as_uint(a[0]), __float_as_uint(a[1]),
                      __float_as_uint(a[2]), __float_as_uint(a[3])};
    unsigned bu[2] = {__float_as_uint(b[0]), __float_as_uint(b[1])};
    mma8(c, au, bu);
}

#define CPA16(dst, src) \
    asm volatile("cp.async.cg.shared.global [%0], [%1], 16;" ::"r"(dst), "l"(src))

// ---------------- elementwise tf32 rounding ----------------
__global__ void cvt_x(const float* __restrict__ in, float* __restrict__ out, int n4) {
    int i = blockIdx.x * blockDim.x + threadIdx.x;
    if (i >= n4) return;
    float4 v = ((const float4*)in)[i];
    v.x = f2tff(v.x); v.y = f2tff(v.y); v.z = f2tff(v.z); v.w = f2tff(v.w);
    ((float4*)out)[i] = v;
}
__global__ void cvt_wkv(const float* __restrict__ wk, const float* __restrict__ wv,
                        float* __restrict__ ok, float* __restrict__ ov) {
    int i = blockIdx.x * blockDim.x + threadIdx.x;
    const float* in = (i < 16384) ? wk : wv;
    float* out = (i < 16384) ? ok : ov;
    int j = (i < 16384) ? i : i - 16384;
    float4 v = ((const float4*)in)[j];
    v.x = f2tff(v.x); v.y = f2tff(v.y); v.z = f2tff(v.z); v.w = f2tff(v.w);
    ((float4*)out)[j] = v;
}

// ---------------- 1024x1024 transpose + tf32 round (wq, wo) ----------------
__global__ void tr1024(const float* __restrict__ a, const float* __restrict__ b,
                       float* __restrict__ ta, float* __restrict__ tb) {
    const float* in = blockIdx.z ? b : a;
    float* out = blockIdx.z ? tb : ta;
    __shared__ float t[32][33];
    int x = blockIdx.x * 32 + threadIdx.x;
    int y0 = blockIdx.y * 32;
    for (int i = threadIdx.y; i < 32; i += 8)
        t[i][threadIdx.x] = in[(y0 + i) * 1024 + x];
    __syncthreads();
    int x2 = y0 + threadIdx.x;
    int y2 = blockIdx.x * 32;
    for (int i = threadIdx.y; i < 32; i += 8)
        out[(y2 + i) * 1024 + x2] = f2tff(t[threadIdx.x][i]);
}

// ---------------- K transpose: [b][s][d] -> [b][d][s] (after rope) ----------------
__global__ void ktr(const float* __restrict__ k, float* __restrict__ kt) {
    __shared__ float t[32][33];
    int b = blockIdx.z;
    int s0 = blockIdx.x * 32, d0 = blockIdx.y * 32;
    for (int i = threadIdx.y; i < 32; i += 8)
        t[i][threadIdx.x] = k[((size_t)b * S + s0 + i) * HD + d0 + threadIdx.x];
    __syncthreads();
    for (int i = threadIdx.y; i < 32; i += 8)
        kt[((size_t)b * HD + d0 + i) * S + s0 + threadIdx.x] = t[threadIdx.x][i];
}

// ---------------- tf32 tensor-core GEMM (operands pre-rounded) ----------------
template <int BN, bool KV, bool CVTOUT>
__global__ void __launch_bounds__(256, 2)
gemm_tc(const float* __restrict__ A, const float* __restrict__ B0,
        float* __restrict__ C0, const float* __restrict__ B1,
        float* __restrict__ C1, int M, int N, int K) {
    constexpr int BM = 128, BK = 32;
    constexpr int BNS = BN + 8;
    constexpr int ASZ = BM * BK;
    constexpr int BSZ = BK * BNS;
    constexpr int NT = BN / 16;
    constexpr int BG = BN / 4;

    extern __shared__ float sm[];
    const int tid = threadIdx.x;
    const int warp = tid >> 5, lane = tid & 31;
    const int gid = lane >> 2, tig = lane & 3;
    const int wm = warp >> 1, wn = warp & 1;

    const float* Bg;
    float* C;
    int bn;
    if (KV) {
        Bg = blockIdx.x ? B1 : B0;
        C = blockIdx.x ? C1 : C0;
        bn = 0;
    } else {
        Bg = B0;
        C = C0;
        bn = blockIdx.x * BN;
    }
    const int bm = blockIdx.y * BM;

    uint32_t sbase = (uint32_t)__cvta_generic_to_shared(sm);

    auto ld_stage = [&](int stage, int k0) {
        uint32_t abase = sbase + stage * ASZ * 4;
        uint32_t bbase = sbase + (2 * ASZ + stage * BSZ) * 4;
#pragma unroll
        for (int t = tid; t < BM * 8; t += 256) {
            int m = t >> 3, g = t & 7;
            int col = (g * 4) ^ ((m & 7) * 4);
            CPA16(abase + (m * 32 + col) * 4, A + (size_t)(bm + m) * K + k0 + g * 4);
        }
#pragma unroll
        for (int t = tid; t < BK * BG; t += 256) {
            int k = t / BG, g = t % BG;
            CPA16(bbase + (k * BNS + g * 4) * 4, Bg + (size_t)(k0 + k) * N + bn + g * 4);
        }
    };

    float acc[2][NT][4];
#pragma unroll
    for (int mt = 0; mt < 2; mt++)
#pragma unroll
        for (int nt = 0; nt < NT; nt++)
#pragma unroll
            for (int c = 0; c < 4; c++) acc[mt][nt][c] = 0.0f;

    const int nk = K / BK;
    ld_stage(0, 0);
    asm volatile("cp.async.commit_group;");

    int buf = 0;
    for (int kt = 0; kt < nk; kt++) {
        if (kt + 1 < nk) {
            ld_stage(buf ^ 1, (kt + 1) * BK);
            asm volatile("cp.async.commit_group;");
            asm volatile("cp.async.wait_group 1;");
        } else {
            asm volatile("cp.async.wait_group 0;");
        }
        __syncthreads();

        const float* As = sm + buf * ASZ;
        const float* Bs = sm + 2 * ASZ + buf * BSZ;
#pragma unroll
        for (int ks = 0; ks < 4; ks++) {
            float a[2][4];
#pragma unroll
            for (int mt = 0; mt < 2; mt++) {
                int m = wm * 32 + mt * 16 + gid;
                int sw = (m & 7) * 4;
                int k0c = ks * 8 + tig;
                a[mt][0] = As[m * 32 + (k0c ^ sw)];
                a[mt][1] = As[(m + 8) * 32 + (k0c ^ sw)];
                a[mt][2] = As[m * 32 + ((k0c + 4) ^ sw)];
                a[mt][3] = As[(m + 8) * 32 + ((k0c + 4) ^ sw)];
            }
#pragma unroll
            for (int nt = 0; nt < NT; nt++) {
                int n = wn * (BN / 2) + nt * 8 + gid;
                float bb[2];
                bb[0] = Bs[(ks * 8 + tig) * BNS + n];
                bb[1] = Bs[(ks * 8 + tig + 4) * BNS + n];
                mma8f(acc[0][nt], a[0], bb);
                mma8f(acc[1][nt], a[1], bb);
            }
        }
        __syncthreads();
        buf ^= 1;
    }

#pragma unroll
    for (int mt = 0; mt < 2; mt++) {
        int row = bm + wm * 32 + mt * 16 + gid;
#pragma unroll
        for (int nt = 0; nt < NT; nt++) {
            int col = bn + wn * (BN / 2) + nt * 8 + tig * 2;
            float o0 = acc[mt][nt][0], o1 = acc[mt][nt][1];
            float o2 = acc[mt][nt][2], o3 = acc[mt][nt][3];
            if (CVTOUT) { o0 = f2tff(o0); o1 = f2tff(o1); o2 = f2tff(o2); o3 = f2tff(o3); }
            *(float2*)&C[(size_t)row * N + col] = make_float2(o0, o1);
            *(float2*)&C[(size_t)(row + 8) * N + col] = make_float2(o2, o3);
        }
    }
}

// ---------------- RoPE (in-place, outputs tf32-rounded) ----------------
__global__ void rope_kernel(float* __restrict__ q, float* __restrict__ k) {
    const long total = (long)B * S * (H + 1) * 32;
    long gtid = (long)blockIdx.x * blockDim.x + threadIdx.x;
    if (gtid >= total) return;
    int lane = (int)(gtid & 31);
    long chunk = gtid >> 5;
    const long nq = (long)B * S * H;

    float* base;
    int s;
    if (chunk < nq) {
        s = (int)((chunk / H) % S);
        base = q + chunk * 64;
    } else {
        long c2 = chunk - nq;
        s = (int)(c2 % S);
        base = k + c2 * 64;
    }
    float freq = powf(1000.0f, -(float)lane / 32.0f);
    float ang = (float)s * freq;
    float sn, cs;
    sincosf(ang, &sn, &cs);
    float t0 = base[2 * lane];
    float t1 = base[2 * lane + 1];
    __syncwarp();
    base[lane] = f2tff(t0 * cs - t1 * sn);
    base[lane + 32] = f2tff(t1 * cs + t0 * sn);
}

// ---------------- tf32 flash attention (causal, MQA) ----------------
// BQ=128, 8 warps x 16 rows. K/V tiles of 64 keys, cp.async double-buffered.
// Q fragments hoisted to registers. smem: Ps[128][72] + 2*(Kt[64][72]+Vs[64][72])
__global__ void __launch_bounds__(256, 2)
attn_tc(const float* __restrict__ q, const float* __restrict__ ktg,
        const float* __restrict__ v, float* __restrict__ o) {
    constexpr int ST = 72;
    constexpr int PSZ = 128 * ST;   // Ps floats
    constexpr int TSZ = 64 * ST;    // one K or V tile
    extern __shared__ float sm[];
    float* Ps = sm;

    const int qt = gridDim.x - 1 - blockIdx.x;
    const int h = blockIdx.y, b = blockIdx.z;
    const int tid = threadIdx.x;
    const int warp = tid >> 5, lane = tid & 31;
    const int gid = lane >> 2, tig = lane & 3;
    const int qbase = qt * 128;
    const float scale = 0.125f;

    uint32_t sbase = (uint32_t)__cvta_generic_to_shared(sm);

    auto fill = [&](int kt_, int stg) {
        int kvb = kt_ * 64;
        uint32_t kb = sbase + (PSZ + stg * 2 * TSZ) * 4;
        uint32_t vb = kb + TSZ * 4;
#pragma unroll
        for (int t = tid; t < 1024; t += 256) {
            int rr = t >> 4, g = t & 15;
            CPA16(kb + (rr * ST + g * 4) * 4, ktg + ((size_t)b * HD + rr) * S + kvb + g * 4);
            CPA16(vb + (rr * ST + g * 4) * 4, v + ((size_t)b * S + kvb + rr) * HD + g * 4);
        }
    };

    // prefetch first K/V tile
    fill(0, 0);
    asm volatile("cp.async.commit_group;");

    // stage Q through Ps, hoist fragments to registers
    for (int t = tid; t < 128 * 16; t += 256) {
        int r = t >> 4, g = t & 15;
        float4 qv = *(const float4*)&q[((size_t)b * S + qbase + r) * D + h * 64 + g * 4];
        qv.x *= scale; qv.y *= scale; qv.z *= scale; qv.w *= scale;
        *(float4*)&Ps[r * ST + g * 4] = qv;
    }
    __syncthreads();
    const int r = warp * 16 + gid;
    float qa[8][4];
#pragma unroll
    for (int ks = 0; ks < 8; ks++) {
        qa[ks][0] = Ps[r * ST + ks * 8 + tig];
        qa[ks][1] = Ps[(r + 8) * ST + ks * 8 + tig];
        qa[ks][2] = Ps[r * ST + ks * 8 + tig + 4];
        qa[ks][3] = Ps[(r + 8) * ST + ks * 8 + tig + 4];
    }

    float m0 = -1e30f, m1 = -1e30f, l0 = 0.0f, l1 = 0.0f;
    float acc[8][4];
#pragma unroll
    for (int nt = 0; nt < 8; nt++)
#pragma unroll
        for (int c = 0; c < 4; c++) acc[nt][c] = 0.0f;

    const int nkt = qt * 2 + 2;
    const int wrow_max = qbase + warp * 16 + 15;  // last query row of this warp

    for (int kt = 0; kt < nkt; kt++) {
        const int cur = kt & 1;
        const int kvbase = kt * 64;
        asm volatile("cp.async.wait_group 0;");
        __syncthreads();
        if (kt + 1 < nkt) {
            fill(kt + 1, cur ^ 1);
            asm volatile("cp.async.commit_group;");
        }

        if (kvbase <= wrow_max) {  // warp has at least one unmasked element
            const float* Kt = sm + PSZ + cur * 2 * TSZ;
            const float* Vs = Kt + TSZ;

            float sv[8][4];
#pragma unroll
            for (int nt = 0; nt < 8; nt++)
#pragma unroll
                for (int c = 0; c < 4; c++) sv[nt][c] = 0.0f;
#pragma unroll
            for (int ks = 0; ks < 8; ks++) {
#pragma unroll
                for (int nt = 0; nt < 8; nt++) {
                    float bb[2];
                    bb[0] = Kt[(ks * 8 + tig) * ST + nt * 8 + gid];
                    bb[1] = Kt[(ks * 8 + tig + 4) * ST + nt * 8 + gid];
                    mma8f(sv[nt], qa[ks], bb);
                }
            }

            if (kt >= nkt - 2) {
                int gr0 = qbase + r, gr1 = gr0 + 8;
#pragma unroll
                for (int nt = 0; nt < 8; nt++) {
                    int col = kvbase + nt * 8 + tig * 2;
                    if (col > gr0) sv[nt][0] = -1e30f;
                    if (col + 1 > gr0) sv[nt][1] = -1e30f;
                    if (col > gr1) sv[nt][2] = -1e30f;
                    if (col + 1 > gr1) sv[nt][3] = -1e30f;
                }
            }

            float rm0 = -1e30f, rm1 = -1e30f;
#pragma unroll
            for (int nt = 0; nt < 8; nt++) {
                rm0 = fmaxf(rm0, fmaxf(sv[nt][0], sv[nt][1]));
                rm1 = fmaxf(rm1, fmaxf(sv[nt][2], sv[nt][3]));
            }
            rm0 = fmaxf(rm0, __shfl_xor_sync(0xffffffffu, rm0, 1));
            rm0 = fmaxf(rm0, __shfl_xor_sync(0xffffffffu, rm0, 2));
            rm1 = fmaxf(rm1, __shfl_xor_sync(0xffffffffu, rm1, 1));
            rm1 = fmaxf(rm1, __shfl_xor_sync(0xffffffffu, rm1, 2));

            float mn0 = fmaxf(m0, rm0), mn1 = fmaxf(m1, rm1);
            float al0 = __expf(m0 - mn0), al1 = __expf(m1 - mn1);
            float rs0 = 0.0f, rs1 = 0.0f;
#pragma unroll
            for (int nt = 0; nt < 8; nt++) {
                float p0 = __expf(sv[nt][0] - mn0);
                float p1 = __expf(sv[nt][1] - mn0);
                float p2 = __expf(sv[nt][2] - mn1);
                float p3 = __expf(sv[nt][3] - mn1);
                rs0 += p0 + p1;
                rs1 += p2 + p3;
                int col = nt * 8 + tig * 2;
                Ps[r * ST + col] = f2tff(p0);
                Ps[r * ST + col + 1] = f2tff(p1);
                Ps[(r + 8) * ST + col] = f2tff(p2);
                Ps[(r + 8) * ST + col + 1] = f2tff(p3);
            }
            rs0 += __shfl_xor_sync(0xffffffffu, rs0, 1);
            rs0 += __shfl_xor_sync(0xffffffffu, rs0, 2);
            rs1 += __shfl_xor_sync(0xffffffffu, rs1, 1);
            rs1 += __shfl_xor_sync(0xffffffffu, rs1, 2);
            l0 = l0 * al0 + rs0;
            l1 = l1 * al1 + rs1;
            m0 = mn0;
            m1 = mn1;
#pragma unroll
            for (int nt = 0; nt < 8; nt++) {
                acc[nt][0] *= al0;
                acc[nt][1] *= al0;
                acc[nt][2] *= al1;
                acc[nt][3] *= al1;
            }
            __syncwarp();

#pragma unroll
            for (int ks = 0; ks < 8; ks++) {
                float a[4];
                a[0] = Ps[r * ST + ks * 8 + tig];
                a[1] = Ps[(r + 8) * ST + ks * 8 + tig];
                a[2] = Ps[r * ST + ks * 8 + tig + 4];
                a[3] = Ps[(r + 8) * ST + ks * 8 + tig + 4];
#pragma unroll
                for (int nt = 0; nt < 8; nt++) {
                    float bb[2];
                    bb[0] = Vs[(ks * 8 + tig) * ST + nt * 8 + gid];
                    bb[1] = Vs[(ks * 8 + tig + 4) * ST + nt * 8 + gid];
                    mma8f(acc[nt], a, bb);
                }
            }
        }
        __syncthreads();
    }

    float inv0 = 1.0f / l0, inv1 = 1.0f / l1;
#pragma unroll
    for (int nt = 0; nt < 8; nt++) {
        int col = h * 64 + nt * 8 + tig * 2;
        *(float2*)&o[((size_t)b * S + qbase + r) * D + col] =
            make_float2(f2tff(acc[nt][0] * inv0), f2tff(acc[nt][1] * inv0));
        *(float2*)&o[((size_t)b * S + qbase + r + 8) * D + col] =
            make_float2(f2tff(acc[nt][2] * inv1), f2tff(acc[nt][3] * inv1));
    }
}

// ---------------- launch ----------------
extern "C" void kernel_launch(void* const* d_in, const int* in_sizes, int n_in,
                              void* d_out, int out_size) {
    const float* x = (const float*)d_in[0];
    const float* wq = (const float*)d_in[1];
    const float* wk = (const float*)d_in[2];
    const float* wv = (const float*)d_in[3];
    const float* wo = (const float*)d_in[4];
    float* out = (float*)d_out;

    float *qp, *kp, *ktp, *vp, *ap, *xp, *wqt, *wot, *wkp, *wvp;
    cudaGetSymbolAddress((void**)&qp, g_q);
    cudaGetSymbolAddress((void**)&kp, g_k);
    cudaGetSymbolAddress((void**)&ktp, g_kt);
    cudaGetSymbolAddress((void**)&vp, g_v);
    cudaGetSymbolAddress((void**)&ap, g_att);
    cudaGetSymbolAddress((void**)&xp, g_x);
    cudaGetSymbolAddress((void**)&wqt, g_wqt);
    cudaGetSymbolAddress((void**)&wot, g_wot);
    cudaGetSymbolAddress((void**)&wkp, g_wk2);
    cudaGetSymbolAddress((void**)&wvp, g_wv2);

    const int M = B * S;  // 4096
    const int SM128 = (2 * 128 * 32 + 2 * 32 * 136) * 4;  // 67584
    const int SM64 = (2 * 128 * 32 + 2 * 32 * 72) * 4;    // 51200
    const int SMATT = (128 * 72 + 4 * 64 * 72) * 4;       // 110592

    cudaFuncSetAttribute(gemm_tc<128, false, false>, cudaFuncAttributeMaxDynamicSharedMemorySize, SM128);
    cudaFuncSetAttribute(gemm_tc<64, true, true>, cudaFuncAttributeMaxDynamicSharedMemorySize, SM64);
    cudaFuncSetAttribute(attn_tc, cudaFuncAttributeMaxDynamicSharedMemorySize, SMATT);

    // pre-round inputs to tf32
    cvt_x<<<(M * D / 4 + 255) / 256, 256>>>(x, xp, M * D / 4);
    cvt_wkv<<<(2 * D * HD / 4 + 255) / 256, 256>>>(wk, wv, wkp, wvp);
    tr1024<<<dim3(32, 32, 2), dim3(32, 8)>>>(wq, wo, wqt, wot);

    // Q = x @ wq^T ; K,V dual projection
    gemm_tc<128, false, false><<<dim3(D / 128, M / 128), 256, SM128>>>(xp, wqt, qp, nullptr, nullptr, M, D, D);
    gemm_tc<64, true, true><<<dim3(2, M / 128), 256, SM64>>>(xp, wkp, kp, wvp, vp, M, HD, D);

    // RoPE then K transpose
    {
        long total = (long)B * S * (H + 1) * 32;
        rope_kernel<<<(unsigned)((total + 255) / 256), 256>>>(qp, kp);
    }
    ktr<<<dim3(S / 32, HD / 32, B), dim3(32, 8)>>>(kp, ktp);

    // attention
    attn_tc<<<dim3(S / 128, H, B), 256, SMATT>>>(qp, ktp, vp, ap);

    // out = att @ wo^T
    gemm_tc<128, false, false><<<dim3(D / 128, M / 128), 256, SM128>>>(ap, wot, out, nullptr, nullptr, M, D, D);
}

// round 7
// speedup vs baseline: 5.2468x; 1.1599x over previous
#include <cuda_runtime.h>
#include <math.h>
#include <stdint.h>

#define B 2
#define S 2048
#define D 1024
#define H 16
#define HD 64

// ---------------- scratch (allocation-free) ----------------
__device__ float g_q[B * S * D];      // 16 MB
__device__ float g_k[B * S * HD];     // 1 MB
__device__ float g_kt[B * HD * S];    // 1 MB   K transposed [b][d][s]
__device__ float g_v[B * S * HD];     // 1 MB
__device__ float g_att[B * S * D];    // 16 MB
__device__ float g_x[B * S * D];      // 16 MB  tf32-rounded x
__device__ float g_wqt[D * D];        // 4 MB   wq^T (tf32)
__device__ float g_wot[D * D];        // 4 MB   wo^T (tf32)
__device__ float g_wk2[D * HD];       // 256 KB wk (tf32)
__device__ float g_wv2[D * HD];       // 256 KB wv (tf32)

// ---------------- helpers ----------------
__device__ __forceinline__ unsigned f2tf(float x) {
    unsigned r;
    asm("cvt.rna.tf32.f32 %0, %1;" : "=r"(r) : "f"(x));
    return r;
}
__device__ __forceinline__ float f2tff(float x) { return __uint_as_float(f2tf(x)); }

__device__ __forceinline__ void mma8(float* c, const unsigned* a, const unsigned* b) {
    asm volatile(
        "mma.sync.aligned.m16n8k8.row.col.f32.tf32.tf32.f32 "
        "{%0,%1,%2,%3}, {%4,%5,%6,%7}, {%8,%9}, {%0,%1,%2,%3};"
        : "+f"(c[0]), "+f"(c[1]), "+f"(c[2]), "+f"(c[3])
        : "r"(a[0]), "r"(a[1]), "r"(a[2]), "r"(a[3]), "r"(b[0]), "r"(b[1]));
}
__device__ __forceinline__ void mma8f(float* c, const float* a, const float* b) {
    unsigned au[4] = {__float_as_uint(a[0]), __float_as_uint(a[1]),
                      __float_as_uint(a[2]), __float_as_uint(a[3])};
    unsigned bu[2] = {__float_as_uint(b[0]), __float_as_uint(b[1])};
    mma8(c, au, bu);
}

#define CPA16(dst, src) \
    asm volatile("cp.async.cg.shared.global [%0], [%1], 16;" ::"r"(dst), "l"(src))

// ---------------- elementwise tf32 rounding ----------------
__global__ void cvt_x(const float* __restrict__ in, float* __restrict__ out, int n4) {
    int i = blockIdx.x * blockDim.x + threadIdx.x;
    if (i >= n4) return;
    float4 v = ((const float4*)in)[i];
    v.x = f2tff(v.x); v.y = f2tff(v.y); v.z = f2tff(v.z); v.w = f2tff(v.w);
    ((float4*)out)[i] = v;
}
__global__ void cvt_wkv(const float* __restrict__ wk, const float* __restrict__ wv,
                        float* __restrict__ ok, float* __restrict__ ov) {
    int i = blockIdx.x * blockDim.x + threadIdx.x;
    const float* in = (i < 16384) ? wk : wv;
    float* out = (i < 16384) ? ok : ov;
    int j = (i < 16384) ? i : i - 16384;
    float4 v = ((const float4*)in)[j];
    v.x = f2tff(v.x); v.y = f2tff(v.y); v.z = f2tff(v.z); v.w = f2tff(v.w);
    ((float4*)out)[j] = v;
}

// ---------------- 1024x1024 transpose + tf32 round (wq, wo) ----------------
__global__ void tr1024(const float* __restrict__ a, const float* __restrict__ b,
                       float* __restrict__ ta, float* __restrict__ tb) {
    const float* in = blockIdx.z ? b : a;
    float* out = blockIdx.z ? tb : ta;
    __shared__ float t[32][33];
    int x = blockIdx.x * 32 + threadIdx.x;
    int y0 = blockIdx.y * 32;
    for (int i = threadIdx.y; i < 32; i += 8)
        t[i][threadIdx.x] = in[(y0 + i) * 1024 + x];
    __syncthreads();
    int x2 = y0 + threadIdx.x;
    int y2 = blockIdx.x * 32;
    for (int i = threadIdx.y; i < 32; i += 8)
        out[(y2 + i) * 1024 + x2] = f2tff(t[threadIdx.x][i]);
}

// ---------------- K transpose: [b][s][d] -> [b][d][s] (after rope) ----------------
__global__ void ktr(const float* __restrict__ k, float* __restrict__ kt) {
    __shared__ float t[32][33];
    int b = blockIdx.z;
    int s0 = blockIdx.x * 32, d0 = blockIdx.y * 32;
    for (int i = threadIdx.y; i < 32; i += 8)
        t[i][threadIdx.x] = k[((size_t)b * S + s0 + i) * HD + d0 + threadIdx.x];
    __syncthreads();
    for (int i = threadIdx.y; i < 32; i += 8)
        kt[((size_t)b * HD + d0 + i) * S + s0 + threadIdx.x] = t[threadIdx.x][i];
}

// ---------------- tf32 tensor-core GEMM (operands pre-rounded) ----------------
template <int BN, bool KV, bool CVTOUT>
__global__ void __launch_bounds__(256, 2)
gemm_tc(const float* __restrict__ A, const float* __restrict__ B0,
        float* __restrict__ C0, const float* __restrict__ B1,
        float* __restrict__ C1, int M, int N, int K) {
    constexpr int BM = 128, BK = 32;
    constexpr int BNS = BN + 8;
    constexpr int ASZ = BM * BK;
    constexpr int BSZ = BK * BNS;
    constexpr int NT = BN / 16;
    constexpr int BG = BN / 4;

    extern __shared__ float sm[];
    const int tid = threadIdx.x;
    const int warp = tid >> 5, lane = tid & 31;
    const int gid = lane >> 2, tig = lane & 3;
    const int wm = warp >> 1, wn = warp & 1;

    const float* Bg;
    float* C;
    int bn;
    if (KV) {
        Bg = blockIdx.x ? B1 : B0;
        C = blockIdx.x ? C1 : C0;
        bn = 0;
    } else {
        Bg = B0;
        C = C0;
        bn = blockIdx.x * BN;
    }
    const int bm = blockIdx.y * BM;

    uint32_t sbase = (uint32_t)__cvta_generic_to_shared(sm);

    auto ld_stage = [&](int stage, int k0) {
        uint32_t abase = sbase + stage * ASZ * 4;
        uint32_t bbase = sbase + (2 * ASZ + stage * BSZ) * 4;
#pragma unroll
        for (int t = tid; t < BM * 8; t += 256) {
            int m = t >> 3, g = t & 7;
            int col = (g * 4) ^ ((m & 7) * 4);
            CPA16(abase + (m * 32 + col) * 4, A + (size_t)(bm + m) * K + k0 + g * 4);
        }
#pragma unroll
        for (int t = tid; t < BK * BG; t += 256) {
            int k = t / BG, g = t % BG;
            CPA16(bbase + (k * BNS + g * 4) * 4, Bg + (size_t)(k0 + k) * N + bn + g * 4);
        }
    };

    float acc[2][NT][4];
#pragma unroll
    for (int mt = 0; mt < 2; mt++)
#pragma unroll
        for (int nt = 0; nt < NT; nt++)
#pragma unroll
            for (int c = 0; c < 4; c++) acc[mt][nt][c] = 0.0f;

    const int nk = K / BK;
    ld_stage(0, 0);
    asm volatile("cp.async.commit_group;");

    int buf = 0;
    for (int kt = 0; kt < nk; kt++) {
        if (kt + 1 < nk) {
            ld_stage(buf ^ 1, (kt + 1) * BK);
            asm volatile("cp.async.commit_group;");
            asm volatile("cp.async.wait_group 1;");
        } else {
            asm volatile("cp.async.wait_group 0;");
        }
        __syncthreads();

        const float* As = sm + buf * ASZ;
        const float* Bs = sm + 2 * ASZ + buf * BSZ;
#pragma unroll
        for (int ks = 0; ks < 4; ks++) {
            float a[2][4];
#pragma unroll
            for (int mt = 0; mt < 2; mt++) {
                int m = wm * 32 + mt * 16 + gid;
                int sw = (m & 7) * 4;
                int k0c = ks * 8 + tig;
                a[mt][0] = As[m * 32 + (k0c ^ sw)];
                a[mt][1] = As[(m + 8) * 32 + (k0c ^ sw)];
                a[mt][2] = As[m * 32 + ((k0c + 4) ^ sw)];
                a[mt][3] = As[(m + 8) * 32 + ((k0c + 4) ^ sw)];
            }
#pragma unroll
            for (int nt = 0; nt < NT; nt++) {
                int n = wn * (BN / 2) + nt * 8 + gid;
                float bb[2];
                bb[0] = Bs[(ks * 8 + tig) * BNS + n];
                bb[1] = Bs[(ks * 8 + tig + 4) * BNS + n];
                mma8f(acc[0][nt], a[0], bb);
                mma8f(acc[1][nt], a[1], bb);
            }
        }
        __syncthreads();
        buf ^= 1;
    }

#pragma unroll
    for (int mt = 0; mt < 2; mt++) {
        int row = bm + wm * 32 + mt * 16 + gid;
#pragma unroll
        for (int nt = 0; nt < NT; nt++) {
            int col = bn + wn * (BN / 2) + nt * 8 + tig * 2;
            float o0 = acc[mt][nt][0], o1 = acc[mt][nt][1];
            float o2 = acc[mt][nt][2], o3 = acc[mt][nt][3];
            if (CVTOUT) { o0 = f2tff(o0); o1 = f2tff(o1); o2 = f2tff(o2); o3 = f2tff(o3); }
            *(float2*)&C[(size_t)row * N + col] = make_float2(o0, o1);
            *(float2*)&C[(size_t)(row + 8) * N + col] = make_float2(o2, o3);
        }
    }
}

// ---------------- RoPE (in-place, outputs tf32-rounded) ----------------
__global__ void rope_kernel(float* __restrict__ q, float* __restrict__ k) {
    const long total = (long)B * S * (H + 1) * 32;
    long gtid = (long)blockIdx.x * blockDim.x + threadIdx.x;
    if (gtid >= total) return;
    int lane = (int)(gtid & 31);
    long chunk = gtid >> 5;
    const long nq = (long)B * S * H;

    float* base;
    int s;
    if (chunk < nq) {
        s = (int)((chunk / H) % S);
        base = q + chunk * 64;
    } else {
        long c2 = chunk - nq;
        s = (int)(c2 % S);
        base = k + c2 * 64;
    }
    float freq = powf(1000.0f, -(float)lane / 32.0f);
    float ang = (float)s * freq;
    float sn, cs;
    sincosf(ang, &sn, &cs);
    float t0 = base[2 * lane];
    float t1 = base[2 * lane + 1];
    __syncwarp();
    base[lane] = f2tff(t0 * cs - t1 * sn);
    base[lane + 32] = f2tff(t1 * cs + t0 * sn);
}

// ---------------- tf32 flash attention (causal, MQA, diagonal-paired) ----------------
// Each block handles TWO query tiles: qt=p and qt=NQT-1-p  -> constant work/block.
// BQ=128, 8 warps x 16 rows. K/V tiles of 64 keys, cp.async double-buffered.
__global__ void __launch_bounds__(256, 2)
attn_tc(const float* __restrict__ q, const float* __restrict__ ktg,
        const float* __restrict__ v, float* __restrict__ o) {
    constexpr int ST = 72;
    constexpr int PSZ = 128 * ST;
    constexpr int TSZ = 64 * ST;
    constexpr int NQT = S / 128;  // 16
    extern __shared__ float sm[];
    float* Ps = sm;

    const int pair = blockIdx.x;  // 0..NQT/2-1
    const int h = blockIdx.y, b = blockIdx.z;
    const int tid = threadIdx.x;
    const int warp = tid >> 5, lane = tid & 31;
    const int gid = lane >> 2, tig = lane & 3;
    const float scale = 0.125f;

    uint32_t sbase = (uint32_t)__cvta_generic_to_shared(sm);

    auto fill = [&](int kt_, int stg) {
        int kvb = kt_ * 64;
        uint32_t kb = sbase + (PSZ + stg * 2 * TSZ) * 4;
        uint32_t vb = kb + TSZ * 4;
#pragma unroll
        for (int t = tid; t < 1024; t += 256) {
            int rr = t >> 4, g = t & 15;
            CPA16(kb + (rr * ST + g * 4) * 4, ktg + ((size_t)b * HD + rr) * S + kvb + g * 4);
            CPA16(vb + (rr * ST + g * 4) * 4, v + ((size_t)b * S + kvb + rr) * HD + g * 4);
        }
    };

    const int r = warp * 16 + gid;

#pragma unroll 1
    for (int half = 0; half < 2; half++) {
        const int qt = half ? (NQT - 1 - pair) : pair;
        const int qbase = qt * 128;
        const int nkt = qt * 2 + 2;

        // prefetch first K/V tile of this half
        fill(0, 0);
        asm volatile("cp.async.commit_group;");

        // stage Q through Ps, hoist fragments to registers
        for (int t = tid; t < 128 * 16; t += 256) {
            int rr = t >> 4, g = t & 15;
            float4 qv = *(const float4*)&q[((size_t)b * S + qbase + rr) * D + h * 64 + g * 4];
            qv.x *= scale; qv.y *= scale; qv.z *= scale; qv.w *= scale;
            *(float4*)&Ps[rr * ST + g * 4] = qv;
        }
        __syncthreads();
        float qa[8][4];
#pragma unroll
        for (int ks = 0; ks < 8; ks++) {
            qa[ks][0] = Ps[r * ST + ks * 8 + tig];
            qa[ks][1] = Ps[(r + 8) * ST + ks * 8 + tig];
            qa[ks][2] = Ps[r * ST + ks * 8 + tig + 4];
            qa[ks][3] = Ps[(r + 8) * ST + ks * 8 + tig + 4];
        }

        float m0 = -1e30f, m1 = -1e30f, l0 = 0.0f, l1 = 0.0f;
        float acc[8][4];
#pragma unroll
        for (int nt = 0; nt < 8; nt++)
#pragma unroll
            for (int c = 0; c < 4; c++) acc[nt][c] = 0.0f;

        const int wrow_max = qbase + warp * 16 + 15;

        for (int kt = 0; kt < nkt; kt++) {
            const int cur = kt & 1;
            const int kvbase = kt * 64;
            asm volatile("cp.async.wait_group 0;");
            __syncthreads();
            if (kt + 1 < nkt) {
                fill(kt + 1, cur ^ 1);
                asm volatile("cp.async.commit_group;");
            }

            if (kvbase <= wrow_max) {
                const float* Kt = sm + PSZ + cur * 2 * TSZ;
                const float* Vs = Kt + TSZ;

                float sv[8][4];
#pragma unroll
                for (int nt = 0; nt < 8; nt++)
#pragma unroll
                    for (int c = 0; c < 4; c++) sv[nt][c] = 0.0f;
#pragma unroll
                for (int ks = 0; ks < 8; ks++) {
#pragma unroll
                    for (int nt = 0; nt < 8; nt++) {
                        float bb[2];
                        bb[0] = Kt[(ks * 8 + tig) * ST + nt * 8 + gid];
                        bb[1] = Kt[(ks * 8 + tig + 4) * ST + nt * 8 + gid];
                        mma8f(sv[nt], qa[ks], bb);
                    }
                }

                if (kt >= nkt - 2) {
                    int gr0 = qbase + r, gr1 = gr0 + 8;
#pragma unroll
                    for (int nt = 0; nt < 8; nt++) {
                        int col = kvbase + nt * 8 + tig * 2;
                        if (col > gr0) sv[nt][0] = -1e30f;
                        if (col + 1 > gr0) sv[nt][1] = -1e30f;
                        if (col > gr1) sv[nt][2] = -1e30f;
                        if (col + 1 > gr1) sv[nt][3] = -1e30f;
                    }
                }

                float rm0 = -1e30f, rm1 = -1e30f;
#pragma unroll
                for (int nt = 0; nt < 8; nt++) {
                    rm0 = fmaxf(rm0, fmaxf(sv[nt][0], sv[nt][1]));
                    rm1 = fmaxf(rm1, fmaxf(sv[nt][2], sv[nt][3]));
                }
                rm0 = fmaxf(rm0, __shfl_xor_sync(0xffffffffu, rm0, 1));
                rm0 = fmaxf(rm0, __shfl_xor_sync(0xffffffffu, rm0, 2));
                rm1 = fmaxf(rm1, __shfl_xor_sync(0xffffffffu, rm1, 1));
                rm1 = fmaxf(rm1, __shfl_xor_sync(0xffffffffu, rm1, 2));

                float mn0 = fmaxf(m0, rm0), mn1 = fmaxf(m1, rm1);
                float al0 = __expf(m0 - mn0), al1 = __expf(m1 - mn1);
                float rs0 = 0.0f, rs1 = 0.0f;
#pragma unroll
                for (int nt = 0; nt < 8; nt++) {
                    float p0 = __expf(sv[nt][0] - mn0);
                    float p1 = __expf(sv[nt][1] - mn0);
                    float p2 = __expf(sv[nt][2] - mn1);
                    float p3 = __expf(sv[nt][3] - mn1);
                    rs0 += p0 + p1;
                    rs1 += p2 + p3;
                    int col = nt * 8 + tig * 2;
                    Ps[r * ST + col] = f2tff(p0);
                    Ps[r * ST + col + 1] = f2tff(p1);
                    Ps[(r + 8) * ST + col] = f2tff(p2);
                    Ps[(r + 8) * ST + col + 1] = f2tff(p3);
                }
                rs0 += __shfl_xor_sync(0xffffffffu, rs0, 1);
                rs0 += __shfl_xor_sync(0xffffffffu, rs0, 2);
                rs1 += __shfl_xor_sync(0xffffffffu, rs1, 1);
                rs1 += __shfl_xor_sync(0xffffffffu, rs1, 2);
                l0 = l0 * al0 + rs0;
                l1 = l1 * al1 + rs1;
                m0 = mn0;
                m1 = mn1;
#pragma unroll
                for (int nt = 0; nt < 8; nt++) {
                    acc[nt][0] *= al0;
                    acc[nt][1] *= al0;
                    acc[nt][2] *= al1;
                    acc[nt][3] *= al1;
                }
                __syncwarp();

#pragma unroll
                for (int ks = 0; ks < 8; ks++) {
                    float a[4];
                    a[0] = Ps[r * ST + ks * 8 + tig];
                    a[1] = Ps[(r + 8) * ST + ks * 8 + tig];
                    a[2] = Ps[r * ST + ks * 8 + tig + 4];
                    a[3] = Ps[(r + 8) * ST + ks * 8 + tig + 4];
#pragma unroll
                    for (int nt = 0; nt < 8; nt++) {
                        float bb[2];
                        bb[0] = Vs[(ks * 8 + tig) * ST + nt * 8 + gid];
                        bb[1] = Vs[(ks * 8 + tig + 4) * ST + nt * 8 + gid];
                        mma8f(acc[nt], a, bb);
                    }
                }
            }
            __syncthreads();
        }

        float inv0 = 1.0f / l0, inv1 = 1.0f / l1;
#pragma unroll
        for (int nt = 0; nt < 8; nt++) {
            int col = h * 64 + nt * 8 + tig * 2;
            *(float2*)&o[((size_t)b * S + qbase + r) * D + col] =
                make_float2(f2tff(acc[nt][0] * inv0), f2tff(acc[nt][1] * inv0));
            *(float2*)&o[((size_t)b * S + qbase + r + 8) * D + col] =
                make_float2(f2tff(acc[nt][2] * inv1), f2tff(acc[nt][3] * inv1));
        }
        __syncthreads();  // protect Ps before next half's Q staging
    }
}

// ---------------- launch ----------------
extern "C" void kernel_launch(void* const* d_in, const int* in_sizes, int n_in,
                              void* d_out, int out_size) {
    const float* x = (const float*)d_in[0];
    const float* wq = (const float*)d_in[1];
    const float* wk = (const float*)d_in[2];
    const float* wv = (const float*)d_in[3];
    const float* wo = (const float*)d_in[4];
    float* out = (float*)d_out;

    float *qp, *kp, *ktp, *vp, *ap, *xp, *wqt, *wot, *wkp, *wvp;
    cudaGetSymbolAddress((void**)&qp, g_q);
    cudaGetSymbolAddress((void**)&kp, g_k);
    cudaGetSymbolAddress((void**)&ktp, g_kt);
    cudaGetSymbolAddress((void**)&vp, g_v);
    cudaGetSymbolAddress((void**)&ap, g_att);
    cudaGetSymbolAddress((void**)&xp, g_x);
    cudaGetSymbolAddress((void**)&wqt, g_wqt);
    cudaGetSymbolAddress((void**)&wot, g_wot);
    cudaGetSymbolAddress((void**)&wkp, g_wk2);
    cudaGetSymbolAddress((void**)&wvp, g_wv2);

    const int M = B * S;  // 4096
    const int SM128 = (2 * 128 * 32 + 2 * 32 * 136) * 4;  // 67584
    const int SM64 = (2 * 128 * 32 + 2 * 32 * 72) * 4;    // 51200
    const int SMATT = (128 * 72 + 4 * 64 * 72) * 4;       // 110592

    cudaFuncSetAttribute(gemm_tc<128, false, false>, cudaFuncAttributeMaxDynamicSharedMemorySize, SM128);
    cudaFuncSetAttribute(gemm_tc<64, true, true>, cudaFuncAttributeMaxDynamicSharedMemorySize, SM64);
    cudaFuncSetAttribute(attn_tc, cudaFuncAttributeMaxDynamicSharedMemorySize, SMATT);

    // pre-round inputs to tf32
    cvt_x<<<(M * D / 4 + 255) / 256, 256>>>(x, xp, M * D / 4);
    cvt_wkv<<<(2 * D * HD / 4 + 255) / 256, 256>>>(wk, wv, wkp, wvp);
    tr1024<<<dim3(32, 32, 2), dim3(32, 8)>>>(wq, wo, wqt, wot);

    // Q = x @ wq^T ; K,V dual projection
    gemm_tc<128, false, false><<<dim3(D / 128, M / 128), 256, SM128>>>(xp, wqt, qp, nullptr, nullptr, M, D, D);
    gemm_tc<64, true, true><<<dim3(2, M / 128), 256, SM64>>>(xp, wkp, kp, wvp, vp, M, HD, D);

    // RoPE then K transpose
    {
        long total = (long)B * S * (H + 1) * 32;
        rope_kernel<<<(unsigned)((total + 255) / 256), 256>>>(qp, kp);
    }
    ktr<<<dim3(S / 32, HD / 32, B), dim3(32, 8)>>>(kp, ktp);

    // attention (diagonal-paired: grid.x = S/256)
    attn_tc<<<dim3(S / 256, H, B), 256, SMATT>>>(qp, ktp, vp, ap);

    // out = att @ wo^T
    gemm_tc<128, false, false><<<dim3(D / 128, M / 128), 256, SM128>>>(ap, wot, out, nullptr, nullptr, M, D, D);
}

// round 9
// speedup vs baseline: 5.3837x; 1.0261x over previous
#include <cuda_runtime.h>
#include <math.h>
#include <stdint.h>

#define B 2
#define S 2048
#define D 1024
#define H 16
#define HD 64

// ---------------- scratch (allocation-free) ----------------
__device__ float g_q[B * S * D];      // 16 MB  roped Q
__device__ float g_kt[B * HD * S];    // 1 MB   roped K, transposed [b][d][s]
__device__ float g_v[B * S * HD];     // 1 MB
__device__ float g_att[B * S * D];    // 16 MB
__device__ float g_x[B * S * D];      // 16 MB  tf32-rounded x
__device__ float g_wqt[D * D];        // 4 MB   wq^T (tf32)
__device__ float g_wot[D * D];        // 4 MB   wo^T (tf32)
__device__ float g_wk2[D * HD];       // 256 KB wk (tf32)
__device__ float g_wv2[D * HD];       // 256 KB wv (tf32)

// ---------------- helpers ----------------
__device__ __forceinline__ unsigned f2tf(float x) {
    unsigned r;
    asm("cvt.rna.tf32.f32 %0, %1;" : "=r"(r) : "f"(x));
    return r;
}
__device__ __forceinline__ float f2tff(float x) { return __uint_as_float(f2tf(x)); }

__device__ __forceinline__ void mma8(float* c, const unsigned* a, const unsigned* b) {
    asm volatile(
        "mma.sync.aligned.m16n8k8.row.col.f32.tf32.tf32.f32 "
        "{%0,%1,%2,%3}, {%4,%5,%6,%7}, {%8,%9}, {%0,%1,%2,%3};"
        : "+f"(c[0]), "+f"(c[1]), "+f"(c[2]), "+f"(c[3])
        : "r"(a[0]), "r"(a[1]), "r"(a[2]), "r"(a[3]), "r"(b[0]), "r"(b[1]));
}
__device__ __forceinline__ void mma8f(float* c, const float* a, const float* b) {
    unsigned au[4] = {__float_as_uint(a[0]), __float_as_uint(a[1]),
                      __float_as_uint(a[2]), __float_as_uint(a[3])};
    unsigned bu[2] = {__float_as_uint(b[0]), __float_as_uint(b[1])};
    mma8(c, au, bu);
}

#define CPA16(dst, src) \
    asm volatile("cp.async.cg.shared.global [%0], [%1], 16;" ::"r"(dst), "l"(src))

#define LOG2_1000_OVER32 (9.965784284662087f / 32.0f)

// ---------------- elementwise tf32 rounding ----------------
__global__ void cvt_x(const float* __restrict__ in, float* __restrict__ out, int n4) {
    int i = blockIdx.x * blockDim.x + threadIdx.x;
    if (i >= n4) return;
    float4 v = ((const float4*)in)[i];
    v.x = f2tff(v.x); v.y = f2tff(v.y); v.z = f2tff(v.z); v.w = f2tff(v.w);
    ((float4*)out)[i] = v;
}
__global__ void cvt_wkv(const float* __restrict__ wk, const float* __restrict__ wv,
                        float* __restrict__ ok, float* __restrict__ ov) {
    int i = blockIdx.x * blockDim.x + threadIdx.x;
    const float* in = (i < 16384) ? wk : wv;
    float* out = (i < 16384) ? ok : ov;
    int j = (i < 16384) ? i : i - 16384;
    float4 v = ((const float4*)in)[j];
    v.x = f2tff(v.x); v.y = f2tff(v.y); v.z = f2tff(v.z); v.w = f2tff(v.w);
    ((float4*)out)[j] = v;
}

// ---------------- 1024x1024 transpose + tf32 round (wq, wo) ----------------
__global__ void tr1024(const float* __restrict__ a, const float* __restrict__ b,
                       float* __restrict__ ta, float* __restrict__ tb) {
    const float* in = blockIdx.z ? b : a;
    float* out = blockIdx.z ? tb : ta;
    __shared__ float t[32][33];
    int x = blockIdx.x * 32 + threadIdx.x;
    int y0 = blockIdx.y * 32;
    for (int i = threadIdx.y; i < 32; i += 8)
        t[i][threadIdx.x] = in[(y0 + i) * 1024 + x];
    __syncthreads();
    int x2 = y0 + threadIdx.x;
    int y2 = blockIdx.x * 32;
    for (int i = threadIdx.y; i < 32; i += 8)
        out[(y2 + i) * 1024 + x2] = f2tff(t[threadIdx.x][i]);
}

// ---------------- shared GEMM body ----------------
// C = A[M,K] * Bg[K,N]. BM=128, BK=32, 256 threads = 8 warps (4m x 2n).
// MODE 0: plain store + tf32 round (V)
// MODE 1: RoPE epilogue, write roped+rounded (Q; N=D, head chunks of 64)
// MODE 2: RoPE epilogue + transpose to [b][d][s] (K; N=HD)
// MODE 3: plain store, no rounding (O-proj -> final output)
template <int BN, int MODE>
__device__ __forceinline__ void gemm_body(
    const float* __restrict__ A, const float* __restrict__ Bg,
    float* __restrict__ C, int bm, int bn, int N, int K, float* sm) {
    constexpr int BM = 128, BK = 32;
    constexpr int BNS = BN + 8;
    constexpr int ASZ = BM * BK;
    constexpr int BSZ = BK * BNS;
    constexpr int NT = BN / 16;
    constexpr int BG = BN / 4;

    const int tid = threadIdx.x;
    const int warp = tid >> 5, lane = tid & 31;
    const int gid = lane >> 2, tig = lane & 3;
    const int wm = warp >> 1, wn = warp & 1;

    uint32_t sbase = (uint32_t)__cvta_generic_to_shared(sm);

    auto ld_stage = [&](int stage, int k0) {
        uint32_t abase = sbase + stage * ASZ * 4;
        uint32_t bbase = sbase + (2 * ASZ + stage * BSZ) * 4;
#pragma unroll
        for (int t = tid; t < BM * 8; t += 256) {
            int m = t >> 3, g = t & 7;
            int col = (g * 4) ^ ((m & 7) * 4);
            CPA16(abase + (m * 32 + col) * 4, A + (size_t)(bm + m) * K + k0 + g * 4);
        }
#pragma unroll
        for (int t = tid; t < BK * BG; t += 256) {
            int k = t / BG, g = t % BG;
            CPA16(bbase + (k * BNS + g * 4) * 4, Bg + (size_t)(k0 + k) * N + bn + g * 4);
        }
    };

    float acc[2][NT][4];
#pragma unroll
    for (int mt = 0; mt < 2; mt++)
#pragma unroll
        for (int nt = 0; nt < NT; nt++)
#pragma unroll
            for (int c = 0; c < 4; c++) acc[mt][nt][c] = 0.0f;

    const int nk = K / BK;
    ld_stage(0, 0);
    asm volatile("cp.async.commit_group;");

    int buf = 0;
    for (int kt = 0; kt < nk; kt++) {
        if (kt + 1 < nk) {
            ld_stage(buf ^ 1, (kt + 1) * BK);
            asm volatile("cp.async.commit_group;");
            asm volatile("cp.async.wait_group 1;");
        } else {
            asm volatile("cp.async.wait_group 0;");
        }
        __syncthreads();

        const float* As = sm + buf * ASZ;
        const float* Bs = sm + 2 * ASZ + buf * BSZ;
#pragma unroll
        for (int ks = 0; ks < 4; ks++) {
            float a[2][4];
#pragma unroll
            for (int mt = 0; mt < 2; mt++) {
                int m = wm * 32 + mt * 16 + gid;
                int sw = (m & 7) * 4;
                int k0c = ks * 8 + tig;
                a[mt][0] = As[m * 32 + (k0c ^ sw)];
                a[mt][1] = As[(m + 8) * 32 + (k0c ^ sw)];
                a[mt][2] = As[m * 32 + ((k0c + 4) ^ sw)];
                a[mt][3] = As[(m + 8) * 32 + ((k0c + 4) ^ sw)];
            }
#pragma unroll
            for (int nt = 0; nt < NT; nt++) {
                int n = wn * (BN / 2) + nt * 8 + gid;
                float bb[2];
                bb[0] = Bs[(ks * 8 + tig) * BNS + n];
                bb[1] = Bs[(ks * 8 + tig + 4) * BNS + n];
                mma8f(acc[0][nt], a[0], bb);
                mma8f(acc[1][nt], a[1], bb);
            }
        }
        __syncthreads();
        buf ^= 1;
    }

    // ---------------- epilogues ----------------
#pragma unroll
    for (int mt = 0; mt < 2; mt++) {
        int r0 = bm + wm * 32 + mt * 16 + gid;
        int r1 = r0 + 8;
#pragma unroll
        for (int nt = 0; nt < NT; nt++) {
            int n = bn + wn * (BN / 2) + nt * 8 + tig * 2;
            float t00 = acc[mt][nt][0], t01 = acc[mt][nt][1];
            float t10 = acc[mt][nt][2], t11 = acc[mt][nt][3];
            if (MODE == 0) {
                *(float2*)&C[(size_t)r0 * N + n] = make_float2(f2tff(t00), f2tff(t01));
                *(float2*)&C[(size_t)r1 * N + n] = make_float2(f2tff(t10), f2tff(t11));
            } else if (MODE == 3) {
                *(float2*)&C[(size_t)r0 * N + n] = make_float2(t00, t01);
                *(float2*)&C[(size_t)r1 * N + n] = make_float2(t10, t11);
            } else {
                int i = (n & 63) >> 1;  // rope freq index within head
                float fr = exp2f(-(float)i * LOG2_1000_OVER32);
                float s0 = (float)(r0 & (S - 1)), s1 = (float)(r1 & (S - 1));
                float sn0, cs0, sn1, cs1;
                sincosf(s0 * fr, &sn0, &cs0);
                sincosf(s1 * fr, &sn1, &cs1);
                float o00 = f2tff(t00 * cs0 - t01 * sn0);
                float o01 = f2tff(t01 * cs0 + t00 * sn0);
                float o10 = f2tff(t10 * cs1 - t11 * sn1);
                float o11 = f2tff(t11 * cs1 + t10 * sn1);
                if (MODE == 1) {  // Q: write to [row][head*64 + i], [.. + 32 + i]
                    int cb = n & ~63;
                    C[(size_t)r0 * N + cb + i] = o00;
                    C[(size_t)r0 * N + cb + 32 + i] = o01;
                    C[(size_t)r1 * N + cb + i] = o10;
                    C[(size_t)r1 * N + cb + 32 + i] = o11;
                } else {  // MODE 2, K: transposed [b][d][s]
                    int b0 = r0 >> 11, sa = r0 & (S - 1);
                    int b1 = r1 >> 11, sb2 = r1 & (S - 1);
                    C[((size_t)b0 * HD + i) * S + sa] = o00;
                    C[((size_t)b0 * HD + 32 + i) * S + sa] = o01;
                    C[((size_t)b1 * HD + i) * S + sb2] = o10;
                    C[((size_t)b1 * HD + 32 + i) * S + sb2] = o11;
                }
            }
        }
    }
}

// ---------------- fused Q/K/V projection (+RoPE, +K-transpose) ----------------
// grid.x = 320: [0,256) Q tiles (8 x 32), [256,320) KV tiles (2 x 32)
__global__ void __launch_bounds__(256, 2)
proj_fused(const float* __restrict__ x, const float* __restrict__ wqt,
           float* __restrict__ q, const float* __restrict__ wk2,
           float* __restrict__ kt, const float* __restrict__ wv2,
           float* __restrict__ v) {
    extern __shared__ float sm[];
    int id = blockIdx.x;
    if (id < 256) {
        gemm_body<128, 1>(x, wqt, q, (id >> 3) * 128, (id & 7) * 128, D, D, sm);
    } else {
        int id2 = id - 256;
        int bm = (id2 >> 1) * 128;
        if (id2 & 1)
            gemm_body<64, 0>(x, wv2, v, bm, 0, HD, D, sm);
        else
            gemm_body<64, 2>(x, wk2, kt, bm, 0, HD, D, sm);
    }
}

// ---------------- O projection ----------------
__global__ void __launch_bounds__(256, 2)
oproj(const float* __restrict__ a, const float* __restrict__ wot,
      float* __restrict__ out) {
    extern __shared__ float sm[];
    gemm_body<128, 3>(a, wot, out, (int)blockIdx.y * 128, (int)blockIdx.x * 128, D, D, sm);
}

// ---------------- tf32 flash attention (causal, MQA, diagonal-paired) ----------------
__global__ void __launch_bounds__(256, 2)
attn_tc(const float* __restrict__ q, const float* __restrict__ ktg,
        const float* __restrict__ v, float* __restrict__ o) {
    constexpr int ST = 72;
    constexpr int PSZ = 128 * ST;
    constexpr int TSZ = 64 * ST;
    constexpr int NQT = S / 128;  // 16
    extern __shared__ float sm[];
    float* Ps = sm;

    const int pair = blockIdx.x;
    const int h = blockIdx.y, b = blockIdx.z;
    const int tid = threadIdx.x;
    const int warp = tid >> 5, lane = tid & 31;
    const int gid = lane >> 2, tig = lane & 3;
    const float scale = 0.125f;

    uint32_t sbase = (uint32_t)__cvta_generic_to_shared(sm);

    auto fill = [&](int kt_, int stg) {
        int kvb = kt_ * 64;
        uint32_t kb = sbase + (PSZ + stg * 2 * TSZ) * 4;
        uint32_t vb = kb + TSZ * 4;
#pragma unroll
        for (int t = tid; t < 1024; t += 256) {
            int rr = t >> 4, g = t & 15;
            CPA16(kb + (rr * ST + g * 4) * 4, ktg + ((size_t)b * HD + rr) * S + kvb + g * 4);
            CPA16(vb + (rr * ST + g * 4) * 4, v + ((size_t)b * S + kvb + rr) * HD + g * 4);
        }
    };

    const int r = warp * 16 + gid;

#pragma unroll 1
    for (int half = 0; half < 2; half++) {
        const int qt = half ? (NQT - 1 - pair) : pair;
        const int qbase = qt * 128;
        const int nkt = qt * 2 + 2;

        fill(0, 0);
        asm volatile("cp.async.commit_group;");

        for (int t = tid; t < 128 * 16; t += 256) {
            int rr = t >> 4, g = t & 15;
            float4 qv = *(const float4*)&q[((size_t)b * S + qbase + rr) * D + h * 64 + g * 4];
            qv.x *= scale; qv.y *= scale; qv.z *= scale; qv.w *= scale;
            *(float4*)&Ps[rr * ST + g * 4] = qv;
        }
        __syncthreads();
        float qa[8][4];
#pragma unroll
        for (int ks = 0; ks < 8; ks++) {
            qa[ks][0] = Ps[r * ST + ks * 8 + tig];
            qa[ks][1] = Ps[(r + 8) * ST + ks * 8 + tig];
            qa[ks][2] = Ps[r * ST + ks * 8 + tig + 4];
            qa[ks][3] = Ps[(r + 8) * ST + ks * 8 + tig + 4];
        }

        float m0 = -1e30f, m1 = -1e30f, l0 = 0.0f, l1 = 0.0f;
        float acc[8][4];
#pragma unroll
        for (int nt = 0; nt < 8; nt++)
#pragma unroll
            for (int c = 0; c < 4; c++) acc[nt][c] = 0.0f;

        const int wrow_max = qbase + warp * 16 + 15;

        for (int kt = 0; kt < nkt; kt++) {
            const int cur = kt & 1;
            const int kvbase = kt * 64;
            asm volatile("cp.async.wait_group 0;");
            __syncthreads();
            if (kt + 1 < nkt) {
                fill(kt + 1, cur ^ 1);
                asm volatile("cp.async.commit_group;");
            }

            if (kvbase <= wrow_max) {
                const float* Kt = sm + PSZ + cur * 2 * TSZ;
                const float* Vs = Kt + TSZ;

                float sv[8][4];
#pragma unroll
                for (int nt = 0; nt < 8; nt++)
#pragma unroll
                    for (int c = 0; c < 4; c++) sv[nt][c] = 0.0f;
#pragma unroll
                for (int ks = 0; ks < 8; ks++) {
#pragma unroll
                    for (int nt = 0; nt < 8; nt++) {
                        float bb[2];
                        bb[0] = Kt[(ks * 8 + tig) * ST + nt * 8 + gid];
                        bb[1] = Kt[(ks * 8 + tig + 4) * ST + nt * 8 + gid];
                        mma8f(sv[nt], qa[ks], bb);
                    }
                }

                if (kt >= nkt - 2) {
                    int gr0 = qbase + r, gr1 = gr0 + 8;
#pragma unroll
                    for (int nt = 0; nt < 8; nt++) {
                        int col = kvbase + nt * 8 + tig * 2;
                        if (col > gr0) sv[nt][0] = -1e30f;
                        if (col + 1 > gr0) sv[nt][1] = -1e30f;
                        if (col > gr1) sv[nt][2] = -1e30f;
                        if (col + 1 > gr1) sv[nt][3] = -1e30f;
                    }
                }

                float rm0 = -1e30f, rm1 = -1e30f;
#pragma unroll
                for (int nt = 0; nt < 8; nt++) {
                    rm0 = fmaxf(rm0, fmaxf(sv[nt][0], sv[nt][1]));
                    rm1 = fmaxf(rm1, fmaxf(sv[nt][2], sv[nt][3]));
                }
                rm0 = fmaxf(rm0, __shfl_xor_sync(0xffffffffu, rm0, 1));
                rm0 = fmaxf(rm0, __shfl_xor_sync(0xffffffffu, rm0, 2));
                rm1 = fmaxf(rm1, __shfl_xor_sync(0xffffffffu, rm1, 1));
                rm1 = fmaxf(rm1, __shfl_xor_sync(0xffffffffu, rm1, 2));

                float mn0 = fmaxf(m0, rm0), mn1 = fmaxf(m1, rm1);
                float al0 = __expf(m0 - mn0), al1 = __expf(m1 - mn1);
                float rs0 = 0.0f, rs1 = 0.0f;
#pragma unroll
                for (int nt = 0; nt < 8; nt++) {
                    float p0 = __expf(sv[nt][0] - mn0);
                    float p1 = __expf(sv[nt][1] - mn0);
                    float p2 = __expf(sv[nt][2] - mn1);
                    float p3 = __expf(sv[nt][3] - mn1);
                    rs0 += p0 + p1;
                    rs1 += p2 + p3;
                    int col = nt * 8 + tig * 2;
                    Ps[r * ST + col] = f2tff(p0);
                    Ps[r * ST + col + 1] = f2tff(p1);
                    Ps[(r + 8) * ST + col] = f2tff(p2);
                    Ps[(r + 8) * ST + col + 1] = f2tff(p3);
                }
                rs0 += __shfl_xor_sync(0xffffffffu, rs0, 1);
                rs0 += __shfl_xor_sync(0xffffffffu, rs0, 2);
                rs1 += __shfl_xor_sync(0xffffffffu, rs1, 1);
                rs1 += __shfl_xor_sync(0xffffffffu, rs1, 2);
                l0 = l0 * al0 + rs0;
                l1 = l1 * al1 + rs1;
                m0 = mn0;
                m1 = mn1;
#pragma unroll
                for (int nt = 0; nt < 8; nt++) {
                    acc[nt][0] *= al0;
                    acc[nt][1] *= al0;
                    acc[nt][2] *= al1;
                    acc[nt][3] *= al1;
                }
                __syncwarp();

#pragma unroll
                for (int ks = 0; ks < 8; ks++) {
                    float a[4];
                    a[0] = Ps[r * ST + ks * 8 + tig];
                    a[1] = Ps[(r + 8) * ST + ks * 8 + tig];
                    a[2] = Ps[r * ST + ks * 8 + tig + 4];
                    a[3] = Ps[(r + 8) * ST + ks * 8 + tig + 4];
#pragma unroll
                    for (int nt = 0; nt < 8; nt++) {
                        float bb[2];
                        bb[0] = Vs[(ks * 8 + tig) * ST + nt * 8 + gid];
                        bb[1] = Vs[(ks * 8 + tig + 4) * ST + nt * 8 + gid];
                        mma8f(acc[nt], a, bb);
                    }
                }
            }
            __syncthreads();
        }

        float inv0 = 1.0f / l0, inv1 = 1.0f / l1;
#pragma unroll
        for (int nt = 0; nt < 8; nt++) {
            int col = h * 64 + nt * 8 + tig * 2;
            *(float2*)&o[((size_t)b * S + qbase + r) * D + col] =
                make_float2(f2tff(acc[nt][0] * inv0), f2tff(acc[nt][1] * inv0));
            *(float2*)&o[((size_t)b * S + qbase + r + 8) * D + col] =
                make_float2(f2tff(acc[nt][2] * inv1), f2tff(acc[nt][3] * inv1));
        }
        __syncthreads();
    }
}

// ---------------- launch ----------------
extern "C" void kernel_launch(void* const* d_in, const int* in_sizes, int n_in,
                              void* d_out, int out_size) {
    const float* x = (const float*)d_in[0];
    const float* wq = (const float*)d_in[1];
    const float* wk = (const float*)d_in[2];
    const float* wv = (const float*)d_in[3];
    const float* wo = (const float*)d_in[4];
    float* out = (float*)d_out;

    float *qp, *ktp, *vp, *ap, *xp, *wqt, *wot, *wkp, *wvp;
    cudaGetSymbolAddress((void**)&qp, g_q);
    cudaGetSymbolAddress((void**)&ktp, g_kt);
    cudaGetSymbolAddress((void**)&vp, g_v);
    cudaGetSymbolAddress((void**)&ap, g_att);
    cudaGetSymbolAddress((void**)&xp, g_x);
    cudaGetSymbolAddress((void**)&wqt, g_wqt);
    cudaGetSymbolAddress((void**)&wot, g_wot);
    cudaGetSymbolAddress((void**)&wkp, g_wk2);
    cudaGetSymbolAddress((void**)&wvp, g_wv2);

    const int M = B * S;  // 4096
    const int SMPROJ = (2 * 128 * 32 + 2 * 32 * 136) * 4;  // 67584 (Q path is larger)
    const int SMATT = (128 * 72 + 4 * 64 * 72) * 4;        // 110592

    cudaFuncSetAttribute(proj_fused, cudaFuncAttributeMaxDynamicSharedMemorySize, SMPROJ);
    cudaFuncSetAttribute(oproj, cudaFuncAttributeMaxDynamicSharedMemorySize, SMPROJ);
    cudaFuncSetAttribute(attn_tc, cudaFuncAttributeMaxDynamicSharedMemorySize, SMATT);

    // pre-round inputs to tf32
    cvt_x<<<(M * D / 4 + 255) / 256, 256>>>(x, xp, M * D / 4);
    cvt_wkv<<<(2 * D * HD / 4 + 255) / 256, 256>>>(wk, wv, wkp, wvp);
    tr1024<<<dim3(32, 32, 2), dim3(32, 8)>>>(wq, wo, wqt, wot);

    // fused Q/K/V projection with RoPE + K-transpose in epilogue
    proj_fused<<<320, 256, SMPROJ>>>(xp, wqt, qp, wkp, ktp, wvp, vp);

    // attention (diagonal-paired)
    attn_tc<<<dim3(S / 256, H, B), 256, SMATT>>>(qp, ktp, vp, ap);

    // out = att @ wo^T
    oproj<<<dim3(D / 128, M / 128), 256, SMPROJ>>>(ap, wot, out);
}